// round 2
// baseline (speedup 1.0000x reference)
#include <cuda_runtime.h>

#define NTOK 768
#define LDIM 8
#define HDIM 64
#define KDIM 4
#define TDIM 3
#define NROWS (NTOK*LDIM)          // 6144
#define HOUT_ELEMS (NROWS*HDIM)    // 393216
#define COUT_OFF HOUT_ELEMS

// -------- scratch (no allocations allowed) --------
__device__ float g_q[NROWS*HDIM];
__device__ float g_k[NROWS*HDIM];
__device__ float g_v[NROWS*HDIM];
__device__ float g_cmv[NROWS*KDIM];
__device__ float g_cmvc[NROWS*KDIM*TDIM];

using u64 = unsigned long long;

__device__ __forceinline__ u64 ffma2(u64 a, u64 b, u64 c) {
    u64 d; asm("fma.rn.f32x2 %0, %1, %2, %3;" : "=l"(d) : "l"(a), "l"(b), "l"(c)); return d;
}
__device__ __forceinline__ u64 pack2(float x, float y) {
    u64 r; asm("mov.b64 %0, {%1, %2};" : "=l"(r) : "f"(x), "f"(y)); return r;
}
__device__ __forceinline__ float2 unpk(u64 v) {
    float2 f; asm("mov.b64 {%0, %1}, %2;" : "=f"(f.x), "=f"(f.y) : "l"(v)); return f;
}

// ==================== Kernel A: fused MLPs ====================
#define ASTR 68   // padded smem row stride (bank-conflict avoidance)

__device__ __forceinline__ void load_w64(const float* __restrict__ wg, float* sW, int tid) {
    float4* d = (float4*)sW;
    const float4* s = (const float4*)wg;
    #pragma unroll
    for (int i = 0; i < 4; i++) d[tid + i*256] = s[tid + i*256];
}

__device__ __forceinline__ void layer64(const float* __restrict__ in, const float* __restrict__ sW,
                                        const float* __restrict__ bg, float* __restrict__ out, int tid) {
    int r = tid >> 3, o0 = (tid & 7) * 8;
    float4 b0 = *(const float4*)&bg[o0];
    float4 b1 = *(const float4*)&bg[o0 + 4];
    u64 acc0 = pack2(b0.x, b0.y), acc1 = pack2(b0.z, b0.w);
    u64 acc2 = pack2(b1.x, b1.y), acc3 = pack2(b1.z, b1.w);
    const float* inr = &in[r*ASTR];
    #pragma unroll 8
    for (int c = 0; c < 64; c++) {
        float hv = inr[c];
        u64 h2 = pack2(hv, hv);
        ulonglong2 wa = *(const ulonglong2*)&sW[c*64 + o0];
        ulonglong2 wb = *(const ulonglong2*)&sW[c*64 + o0 + 4];
        acc0 = ffma2(h2, wa.x, acc0);
        acc1 = ffma2(h2, wa.y, acc1);
        acc2 = ffma2(h2, wb.x, acc2);
        acc3 = ffma2(h2, wb.y, acc3);
    }
    float2 f0 = unpk(acc0), f1 = unpk(acc1), f2 = unpk(acc2), f3 = unpk(acc3);
    f0.x = fmaxf(f0.x, 0.f); f0.y = fmaxf(f0.y, 0.f);
    f1.x = fmaxf(f1.x, 0.f); f1.y = fmaxf(f1.y, 0.f);
    f2.x = fmaxf(f2.x, 0.f); f2.y = fmaxf(f2.y, 0.f);
    f3.x = fmaxf(f3.x, 0.f); f3.y = fmaxf(f3.y, 0.f);
    float* o = &out[r*ASTR + o0];
    *(float4*)o       = make_float4(f0.x, f0.y, f1.x, f1.y);
    *(float4*)(o + 4) = make_float4(f2.x, f2.y, f3.x, f3.y);
}

__device__ __forceinline__ void store_g(const float* __restrict__ in, float* __restrict__ g, int row0, int tid) {
    int r = tid >> 3, c0 = (tid & 7) * 8;
    const float* s = &in[r*ASTR + c0];
    float4 a = *(const float4*)s, b = *(const float4*)(s + 4);
    float4* d = (float4*)&g[(row0 + r)*HDIM + c0];
    d[0] = a; d[1] = b;
}

__global__ __launch_bounds__(256) void mlp_kernel(
    const float* __restrict__ h, const float* __restrict__ coord,
    const float* __restrict__ wq1, const float* __restrict__ bq1,
    const float* __restrict__ wq2, const float* __restrict__ bq2,
    const float* __restrict__ wk1, const float* __restrict__ bk1,
    const float* __restrict__ wk2, const float* __restrict__ bk2,
    const float* __restrict__ wv1, const float* __restrict__ bv1,
    const float* __restrict__ wv2, const float* __restrict__ bv2,
    const float* __restrict__ wc1, const float* __restrict__ bc1,
    const float* __restrict__ wc2)
{
    __shared__ float sIn[32*ASTR];
    __shared__ float sT1[32*ASTR];
    __shared__ float sT2[32*ASTR];
    __shared__ float sW[64*64];
    int tid = threadIdx.x;
    int row0 = blockIdx.x * 32;

    // load h tile (32 x 64)
    {
        int r = tid >> 3, c0 = (tid & 7) * 8;
        const float4* src = (const float4*)&h[(row0 + r)*HDIM + c0];
        float4 a = src[0], b = src[1];
        float* dst = &sIn[r*ASTR + c0];
        *(float4*)dst = a; *(float4*)(dst + 4) = b;
    }
    load_w64(wq1, sW, tid);
    __syncthreads();

    // q chain
    layer64(sIn, sW, bq1, sT1, tid); __syncthreads();
    load_w64(wq2, sW, tid); __syncthreads();
    layer64(sT1, sW, bq2, sT2, tid);
    store_g(sT2, g_q, row0, tid);
    __syncthreads();

    // k chain
    load_w64(wk1, sW, tid); __syncthreads();
    layer64(sIn, sW, bk1, sT1, tid); __syncthreads();
    load_w64(wk2, sW, tid); __syncthreads();
    layer64(sT1, sW, bk2, sT2, tid);
    store_g(sT2, g_k, row0, tid);
    __syncthreads();

    // v chain
    load_w64(wv1, sW, tid); __syncthreads();
    layer64(sIn, sW, bv1, sT1, tid); __syncthreads();
    load_w64(wv2, sW, tid); __syncthreads();
    layer64(sT1, sW, bv2, sT2, tid);
    store_g(sT2, g_v, row0, tid);
    __syncthreads();

    // coord mlp hidden: relu(v @ wc1 + bc1)
    load_w64(wc1, sW, tid); __syncthreads();
    layer64(sT2, sW, bc1, sT1, tid);
    __syncthreads();

    // final: cmv = hidden @ wc2  (64 -> 4, no bias, no relu)
    if (tid < 64) ((float4*)sW)[tid] = ((const float4*)wc2)[tid];
    __syncthreads();
    if (tid < 128) {
        int r = tid >> 2, o = tid & 3;
        float acc = 0.f;
        const float* inr = &sT1[r*ASTR];
        #pragma unroll 8
        for (int c = 0; c < 64; c++) acc += inr[c] * sW[c*4 + o];
        int row = row0 + r;
        g_cmv[row*4 + o] = acc;
        #pragma unroll
        for (int t = 0; t < 3; t++) {
            float cv = coord[row*12 + o*3 + t];
            g_cmvc[row*12 + o*3 + t] = acc * cv;
        }
    }
}

// ==================== Kernel B: attention + aggregation ====================
#define TI 32
#define TJ 64
#define SSTR 778   // padded stride: conflict-free row reads in aggregate phase
#define KSTR 65
#define VSTR 80

#define OFF_QT   0
#define OFF_K    2048            // 64*32
#define OFF_VT   (OFF_K + 64*KSTR)      // 6208
#define OFF_S    (OFF_VT + 64*VSTR)     // 11328
#define OFF_RINV (OFF_S + 32*SSTR)      // 36224
#define OFF_STG  (OFF_RINV + 32)        // 36256
#define SMEM_B_FLOATS (OFF_STG + 32*16) // 36768
#define SMEM_B_BYTES (SMEM_B_FLOATS * 4)

__global__ __launch_bounds__(256) void attn_kernel(
    const float* __restrict__ hin, const float* __restrict__ coord,
    float* __restrict__ out)
{
    extern __shared__ float smem[];
    float* qT    = smem + OFF_QT;
    float* kpad  = smem + OFF_K;
    float* vt    = smem + OFF_VT;
    float* s     = smem + OFF_S;
    float* rinv  = smem + OFF_RINV;
    float* stage = smem + OFF_STG;

    int tid = threadIdx.x;
    int it = blockIdx.x;       // 0..23
    int l  = blockIdx.y;       // 0..7
    int i0 = it * TI;

    // load q tile transposed: qT[c][r]
    {
        int r = tid >> 3, c0 = (tid & 7) * 8;
        const float* src = &g_q[((i0 + r)*LDIM + l)*HDIM + c0];
        float4 a = *(const float4*)src;
        float4 b = *(const float4*)(src + 4);
        float v8[8] = {a.x, a.y, a.z, a.w, b.x, b.y, b.z, b.w};
        #pragma unroll
        for (int u = 0; u < 8; u++) qT[(c0 + u)*TI + r] = v8[u];
    }

    int rg = tid & 7;
    int jg = tid >> 3;
    int r0 = rg * 4;
    int jj = jg * 2;

    // ---- Phase 1: scores ----
    for (int jt = 0; jt < NTOK/TJ; jt++) {
        {
            int j = tid >> 2, c0 = (tid & 3) * 16;
            const float* src = &g_k[((jt*TJ + j)*LDIM + l)*HDIM + c0];
            float* drow = &kpad[j*KSTR + c0];
            #pragma unroll
            for (int q4 = 0; q4 < 4; q4++) {
                float4 a = *(const float4*)(src + q4*4);
                drow[q4*4 + 0] = a.x; drow[q4*4 + 1] = a.y;
                drow[q4*4 + 2] = a.z; drow[q4*4 + 3] = a.w;
            }
        }
        __syncthreads();
        u64 a00 = 0, a01 = 0, a10 = 0, a11 = 0;
        const float* kr0 = &kpad[jj*KSTR];
        const float* kr1 = &kpad[(jj + 1)*KSTR];
        #pragma unroll 8
        for (int c = 0; c < 64; c++) {
            u64 q01 = *(const u64*)&qT[c*TI + r0];
            u64 q23 = *(const u64*)&qT[c*TI + r0 + 2];
            float k0v = kr0[c], k1v = kr1[c];
            u64 k0 = pack2(k0v, k0v);
            u64 k1 = pack2(k1v, k1v);
            a00 = ffma2(q01, k0, a00);
            a01 = ffma2(q23, k0, a01);
            a10 = ffma2(q01, k1, a10);
            a11 = ffma2(q23, k1, a11);
        }
        int jb = jt*TJ + jj;
        float2 f;
        f = unpk(a00); s[(r0+0)*SSTR + jb]     = f.x; s[(r0+1)*SSTR + jb]     = f.y;
        f = unpk(a01); s[(r0+2)*SSTR + jb]     = f.x; s[(r0+3)*SSTR + jb]     = f.y;
        f = unpk(a10); s[(r0+0)*SSTR + jb + 1] = f.x; s[(r0+1)*SSTR + jb + 1] = f.y;
        f = unpk(a11); s[(r0+2)*SSTR + jb + 1] = f.x; s[(r0+3)*SSTR + jb + 1] = f.y;
        __syncthreads();
    }

    // ---- Phase 2: softmax over j (unnormalized exp kept in s; 1/sum in rinv) ----
    {
        int row = tid >> 3, sub = tid & 7;
        float* srow = &s[row*SSTR];
        float m = -1e30f;
        for (int j = sub; j < NTOK; j += 8) m = fmaxf(m, srow[j]);
        #pragma unroll
        for (int w = 4; w >= 1; w >>= 1) m = fmaxf(m, __shfl_xor_sync(0xffffffffu, m, w));
        float sum = 0.f;
        for (int j = sub; j < NTOK; j += 8) {
            float e = __expf(srow[j] - m);
            srow[j] = e;
            sum += e;
        }
        #pragma unroll
        for (int w = 4; w >= 1; w >>= 1) sum += __shfl_xor_sync(0xffffffffu, sum, w);
        if (sub == 0) rinv[row] = 1.0f / sum;
    }
    __syncthreads();

    // ---- Phase 3: aggregation against [v(64)|cmv(4)|cmv*coord(12)] ----
    int ra = tid & 15, dg = tid >> 4;      // rows {ra, ra+16}, d-chunk dg*4
    bool hasE = (dg < 4);                   // warps 0,1 also own d-chunks 64..79
    u64 accA0 = 0, accA1 = 0, accB0 = 0, accB1 = 0;
    u64 accA2 = 0, accA3 = 0, accB2 = 0, accB3 = 0;
    const float* sa = &s[ra*SSTR];
    const float* sb = &s[(ra + 16)*SSTR];

    for (int jt = 0; jt < NTOK/TJ; jt++) {
        {
            int j = tid >> 2, p = (tid & 3) * 16;
            const float* src = &g_v[((jt*TJ + j)*LDIM + l)*HDIM + p];
            float* d = &vt[j*VSTR + p];
            #pragma unroll
            for (int q4 = 0; q4 < 4; q4++)
                *(float4*)(d + q4*4) = *(const float4*)(src + q4*4);
        }
        if (tid < TJ) {
            int j = tid;
            int grow = (jt*TJ + j)*LDIM + l;
            *(float4*)&vt[j*VSTR + 64] = *(const float4*)&g_cmv[grow*4];
            const float* cc = &g_cmvc[grow*12];
            *(float4*)&vt[j*VSTR + 68] = *(const float4*)cc;
            *(float4*)&vt[j*VSTR + 72] = *(const float4*)(cc + 4);
            *(float4*)&vt[j*VSTR + 76] = *(const float4*)(cc + 8);
        }
        __syncthreads();
        const float* vbase = vt + dg*4;
        const float* saj = sa + jt*TJ;
        const float* sbj = sb + jt*TJ;
        #pragma unroll 4
        for (int j = 0; j < TJ; j++) {
            float pa = saj[j], pb = sbj[j];
            u64 pa2 = pack2(pa, pa), pb2 = pack2(pb, pb);
            ulonglong2 v01 = *(const ulonglong2*)&vbase[j*VSTR];
            accA0 = ffma2(pa2, v01.x, accA0);
            accA1 = ffma2(pa2, v01.y, accA1);
            accB0 = ffma2(pb2, v01.x, accB0);
            accB1 = ffma2(pb2, v01.y, accB1);
            if (hasE) {
                ulonglong2 v23 = *(const ulonglong2*)&vbase[j*VSTR + 64];
                accA2 = ffma2(pa2, v23.x, accA2);
                accA3 = ffma2(pa2, v23.y, accA3);
                accB2 = ffma2(pb2, v23.x, accB2);
                accB3 = ffma2(pb2, v23.y, accB3);
            }
        }
        __syncthreads();
    }

    // ---- Epilogue ----
    float invA = rinv[ra], invB = rinv[ra + 16];
    {
        int d0 = dg*4;
        int ia = i0 + ra;
        int ib = i0 + ra + 16;
        float2 x0 = unpk(accA0), x1 = unpk(accA1);
        float4 hv = *(const float4*)&hin[(ia*LDIM + l)*HDIM + d0];
        *(float4*)&out[(ia*LDIM + l)*HDIM + d0] =
            make_float4(hv.x + x0.x*invA, hv.y + x0.y*invA,
                        hv.z + x1.x*invA, hv.w + x1.y*invA);
        float2 y0 = unpk(accB0), y1 = unpk(accB1);
        float4 hw = *(const float4*)&hin[(ib*LDIM + l)*HDIM + d0];
        *(float4*)&out[(ib*LDIM + l)*HDIM + d0] =
            make_float4(hw.x + y0.x*invB, hw.y + y0.y*invB,
                        hw.z + y1.x*invB, hw.w + y1.y*invB);
    }
    if (hasE) {
        int d0 = dg*4;
        float2 e0 = unpk(accA2), e1 = unpk(accA3);
        stage[ra*16 + d0 + 0] = e0.x*invA;
        stage[ra*16 + d0 + 1] = e0.y*invA;
        stage[ra*16 + d0 + 2] = e1.x*invA;
        stage[ra*16 + d0 + 3] = e1.y*invA;
        float2 g0 = unpk(accB2), g1 = unpk(accB3);
        stage[(ra+16)*16 + d0 + 0] = g0.x*invB;
        stage[(ra+16)*16 + d0 + 1] = g0.y*invB;
        stage[(ra+16)*16 + d0 + 2] = g1.x*invB;
        stage[(ra+16)*16 + d0 + 3] = g1.y*invB;
    }
    __syncthreads();
    // coord out: out = coord*(1+S1[k]) - S2[k][t]
    for (int e = tid; e < TI*12; e += 256) {
        int row = e / 12, idx = e % 12, k = idx / 3;
        float S1 = stage[row*16 + k];
        float S2 = stage[row*16 + 4 + idx];
        int off = ((i0 + row)*LDIM + l)*12 + idx;
        out[COUT_OFF + off] = coord[off] * (1.f + S1) - S2;
    }
}

// ==================== launch ====================
extern "C" void kernel_launch(void* const* d_in, const int* in_sizes, int n_in,
                              void* d_out, int out_size) {
    const float* h     = (const float*)d_in[0];
    const float* coord = (const float*)d_in[1];
    const float* wq1 = (const float*)d_in[2];
    const float* bq1 = (const float*)d_in[3];
    const float* wq2 = (const float*)d_in[4];
    const float* bq2 = (const float*)d_in[5];
    const float* wk1 = (const float*)d_in[6];
    const float* bk1 = (const float*)d_in[7];
    const float* wk2 = (const float*)d_in[8];
    const float* bk2 = (const float*)d_in[9];
    const float* wv1 = (const float*)d_in[10];
    const float* bv1 = (const float*)d_in[11];
    const float* wv2 = (const float*)d_in[12];
    const float* bv2 = (const float*)d_in[13];
    const float* wc1 = (const float*)d_in[14];
    const float* bc1 = (const float*)d_in[15];
    const float* wc2 = (const float*)d_in[16];
    float* out = (float*)d_out;

    mlp_kernel<<<NROWS/32, 256>>>(h, coord, wq1, bq1, wq2, bq2,
                                  wk1, bk1, wk2, bk2, wv1, bv1, wv2, bv2,
                                  wc1, bc1, wc2);

    cudaFuncSetAttribute(attn_kernel, cudaFuncAttributeMaxDynamicSharedMemorySize, SMEM_B_BYTES);
    attn_kernel<<<dim3(NTOK/TI, LDIM), 256, SMEM_B_BYTES>>>(h, coord, out);
}

// round 5
// speedup vs baseline: 1.9141x; 1.9141x over previous
#include <cuda_runtime.h>

#define NTOK 768
#define LDIM 8
#define HDIM 64
#define NROWS (NTOK*LDIM)          // 6144
#define HOUT_ELEMS (NROWS*HDIM)    // 393216
#define COUT_OFF HOUT_ELEMS

#define TI 32
#define TJ 64
#define JSPLIT 3
#define TPS 4                      // tiles per split (12 total / 3)
#define NIT (NTOK/TI)              // 24
#define SLOTS (NIT*LDIM*JSPLIT)    // 576
#define VW 80

// -------- scratch (no allocations allowed) --------
__device__ float g_q[NROWS*HDIM];
__device__ float g_k[NROWS*HDIM];
__device__ float g_v[NROWS*HDIM];
__device__ float g_cmv[NROWS*4];
__device__ float g_cmvc[NROWS*12];
__device__ float g_acc[SLOTS*VW*TI];   // [slot][d][row] for coalescing
__device__ float g_mx[SLOTS*TI];
__device__ float g_sm[SLOTS*TI];

using u64 = unsigned long long;

__device__ __forceinline__ u64 ffma2(u64 a, u64 b, u64 c) {
    u64 d; asm("fma.rn.f32x2 %0, %1, %2, %3;" : "=l"(d) : "l"(a), "l"(b), "l"(c)); return d;
}
__device__ __forceinline__ u64 mul2(u64 a, u64 b) {
    u64 d; asm("mul.rn.f32x2 %0, %1, %2;" : "=l"(d) : "l"(a), "l"(b)); return d;
}
__device__ __forceinline__ u64 pack2(float x, float y) {
    u64 r; asm("mov.b64 %0, {%1, %2};" : "=l"(r) : "f"(x), "f"(y)); return r;
}
__device__ __forceinline__ float2 unpk(u64 v) {
    float2 f; asm("mov.b64 {%0, %1}, %2;" : "=f"(f.x), "=f"(f.y) : "l"(v)); return f;
}

// ==================== Kernel A: MLPs, chain-split ====================
#define ASTR 68

__device__ __forceinline__ void load_w64(const float* __restrict__ wg, float* sW, int tid) {
    float4* d = (float4*)sW;
    const float4* s = (const float4*)wg;
    #pragma unroll
    for (int i = 0; i < 4; i++) d[tid + i*256] = s[tid + i*256];
}

__device__ __forceinline__ void layer64(const float* __restrict__ in, const float* __restrict__ sW,
                                        const float* __restrict__ bg, float* __restrict__ out, int tid) {
    int r = tid >> 3, o0 = (tid & 7) * 8;
    float4 b0 = *(const float4*)&bg[o0];
    float4 b1 = *(const float4*)&bg[o0 + 4];
    u64 acc0 = pack2(b0.x, b0.y), acc1 = pack2(b0.z, b0.w);
    u64 acc2 = pack2(b1.x, b1.y), acc3 = pack2(b1.z, b1.w);
    const float* inr = &in[r*ASTR];
    #pragma unroll 8
    for (int c = 0; c < 64; c++) {
        float hv = inr[c];
        u64 h2 = pack2(hv, hv);
        ulonglong2 wa = *(const ulonglong2*)&sW[c*64 + o0];
        ulonglong2 wb = *(const ulonglong2*)&sW[c*64 + o0 + 4];
        acc0 = ffma2(h2, wa.x, acc0);
        acc1 = ffma2(h2, wa.y, acc1);
        acc2 = ffma2(h2, wb.x, acc2);
        acc3 = ffma2(h2, wb.y, acc3);
    }
    float2 f0 = unpk(acc0), f1 = unpk(acc1), f2 = unpk(acc2), f3 = unpk(acc3);
    f0.x = fmaxf(f0.x, 0.f); f0.y = fmaxf(f0.y, 0.f);
    f1.x = fmaxf(f1.x, 0.f); f1.y = fmaxf(f1.y, 0.f);
    f2.x = fmaxf(f2.x, 0.f); f2.y = fmaxf(f2.y, 0.f);
    f3.x = fmaxf(f3.x, 0.f); f3.y = fmaxf(f3.y, 0.f);
    float* o = &out[r*ASTR + o0];
    *(float4*)o       = make_float4(f0.x, f0.y, f1.x, f1.y);
    *(float4*)(o + 4) = make_float4(f2.x, f2.y, f3.x, f3.y);
}

__device__ __forceinline__ void store_g(const float* __restrict__ in, float* __restrict__ g, int row0, int tid) {
    int r = tid >> 3, c0 = (tid & 7) * 8;
    const float* s = &in[r*ASTR + c0];
    float4 a = *(const float4*)s, b = *(const float4*)(s + 4);
    float4* d = (float4*)&g[(row0 + r)*HDIM + c0];
    d[0] = a; d[1] = b;
}

__global__ __launch_bounds__(256) void mlp_kernel(
    const float* __restrict__ h, const float* __restrict__ coord,
    const float* __restrict__ wq1, const float* __restrict__ bq1,
    const float* __restrict__ wq2, const float* __restrict__ bq2,
    const float* __restrict__ wk1, const float* __restrict__ bk1,
    const float* __restrict__ wk2, const float* __restrict__ bk2,
    const float* __restrict__ wv1, const float* __restrict__ bv1,
    const float* __restrict__ wv2, const float* __restrict__ bv2,
    const float* __restrict__ wc1, const float* __restrict__ bc1,
    const float* __restrict__ wc2)
{
    __shared__ float sIn[32*ASTR];
    __shared__ float sT1[32*ASTR];
    __shared__ float sT2[32*ASTR];
    __shared__ float sW[64*64];
    int tid = threadIdx.x;
    int row0 = blockIdx.x * 32;
    int chain = blockIdx.y;

    // load h tile (32 x 64)
    {
        int r = tid >> 3, c0 = (tid & 7) * 8;
        const float4* src = (const float4*)&h[(row0 + r)*HDIM + c0];
        float4 a = src[0], b = src[1];
        float* dst = &sIn[r*ASTR + c0];
        *(float4*)dst = a; *(float4*)(dst + 4) = b;
    }

    const float *w1, *b1, *w2, *b2;
    float* gout;
    if (chain == 0)      { w1 = wq1; b1 = bq1; w2 = wq2; b2 = bq2; gout = g_q; }
    else if (chain == 1) { w1 = wk1; b1 = bk1; w2 = wk2; b2 = bk2; gout = g_k; }
    else                 { w1 = wv1; b1 = bv1; w2 = wv2; b2 = bv2; gout = g_v; }

    load_w64(w1, sW, tid);
    __syncthreads();
    layer64(sIn, sW, b1, sT1, tid);
    __syncthreads();
    load_w64(w2, sW, tid);
    __syncthreads();
    layer64(sT1, sW, b2, sT2, tid);
    store_g(sT2, gout, row0, tid);

    if (chain == 2) {
        __syncthreads();
        load_w64(wc1, sW, tid);
        __syncthreads();
        layer64(sT2, sW, bc1, sT1, tid);
        __syncthreads();
        if (tid < 64) ((float4*)sW)[tid] = ((const float4*)wc2)[tid];
        __syncthreads();
        if (tid < 128) {
            int r = tid >> 2, o = tid & 3;
            float acc = 0.f;
            const float* inr = &sT1[r*ASTR];
            #pragma unroll 8
            for (int c = 0; c < 64; c++) acc += inr[c] * sW[c*4 + o];
            int row = row0 + r;
            g_cmv[row*4 + o] = acc;
            #pragma unroll
            for (int t = 0; t < 3; t++) {
                float cv = coord[row*12 + o*3 + t];
                g_cmvc[row*12 + o*3 + t] = acc * cv;
            }
        }
    }
}

// ==================== Kernel B1: flash attention partials ====================
#define KSTR 68   // multiple of 4: float4 row stores stay 16B-aligned (R2 trap fix)
#define SSTR 33

#define OQT 0
#define OK  2048                    // 64 cols x 32 rows
#define OV  (OK + TJ*KSTR)          // 6400
#define OS  (OV + TJ*VW)            // 11520
#define OC  (OS + TJ*SSTR)          // 13632
#define B1_FLOATS (OC + TI)         // 13664
#define B1_BYTES (B1_FLOATS*4)      // 54656

__global__ __launch_bounds__(256, 4) void attn_part_kernel()
{
    extern __shared__ float smf[];
    float* qT = smf + OQT;
    float* kp = smf + OK;
    float* vt = smf + OV;
    float* S  = smf + OS;
    float* cb = smf + OC;

    int tid = threadIdx.x;
    int it = blockIdx.x, l = blockIdx.y, sp = blockIdx.z;
    int i0 = it * TI;
    int j0 = sp * (TPS*TJ);

    // load q tile transposed: qT[c][r]
    {
        int r = tid >> 3, c0 = (tid & 7) * 8;
        const float* src = &g_q[((i0 + r)*LDIM + l)*HDIM + c0];
        float4 a = *(const float4*)src;
        float4 b = *(const float4*)(src + 4);
        float v8[8] = {a.x, a.y, a.z, a.w, b.x, b.y, b.z, b.w};
        #pragma unroll
        for (int u = 0; u < 8; u++) qT[(c0 + u)*TI + r] = v8[u];
    }

    int rg = tid & 7, jg = tid >> 3, r0 = rg * 4, jj = jg * 2;  // phase1 roles
    int row = tid >> 3, sub = tid & 7;                          // phase2 roles
    int ra = tid & 31, dg = tid >> 5;                           // phase3 roles

    float m_reg = -1e30f, s_reg = 0.f;
    u64 ac[5] = {0, 0, 0, 0, 0};

    for (int t = 0; t < TPS; t++) {
        int jb = j0 + t*TJ;
        // load K tile (64 x 64, padded stride 68)
        {
            int j = tid >> 2, c0 = (tid & 3) * 16;
            const float* src = &g_k[((jb + j)*LDIM + l)*HDIM + c0];
            float* d = &kp[j*KSTR + c0];
            #pragma unroll
            for (int q4 = 0; q4 < 4; q4++)
                *(float4*)(d + q4*4) = *(const float4*)(src + q4*4);
        }
        // load V fused tile (64 x 80): [v(64)|cmv(4)|cmvc(12)]
        {
            int j = tid >> 2, c0 = (tid & 3) * 16;
            const float* src = &g_v[((jb + j)*LDIM + l)*HDIM + c0];
            float* d = &vt[j*VW + c0];
            #pragma unroll
            for (int q4 = 0; q4 < 4; q4++)
                *(float4*)(d + q4*4) = *(const float4*)(src + q4*4);
        }
        if (tid < TJ) {
            int grow = (jb + tid)*LDIM + l;
            *(float4*)&vt[tid*VW + 64] = *(const float4*)&g_cmv[grow*4];
            const float* cc = &g_cmvc[grow*12];
            *(float4*)&vt[tid*VW + 68] = *(const float4*)cc;
            *(float4*)&vt[tid*VW + 72] = *(const float4*)(cc + 4);
            *(float4*)&vt[tid*VW + 76] = *(const float4*)(cc + 8);
        }
        __syncthreads();

        // ---- phase 1: scores -> S[j][r] (transposed) ----
        {
            u64 a00 = 0, a01 = 0, a10 = 0, a11 = 0;
            const float* kr0 = &kp[jj*KSTR];
            const float* kr1 = &kp[(jj + 1)*KSTR];
            #pragma unroll 8
            for (int c = 0; c < 64; c++) {
                u64 q01 = *(const u64*)&qT[c*TI + r0];
                u64 q23 = *(const u64*)&qT[c*TI + r0 + 2];
                float k0v = kr0[c], k1v = kr1[c];
                u64 k0 = pack2(k0v, k0v);
                u64 k1 = pack2(k1v, k1v);
                a00 = ffma2(q01, k0, a00);
                a01 = ffma2(q23, k0, a01);
                a10 = ffma2(q01, k1, a10);
                a11 = ffma2(q23, k1, a11);
            }
            float2 f;
            f = unpk(a00); S[jj*SSTR + r0]     = f.x; S[jj*SSTR + r0 + 1]     = f.y;
            f = unpk(a01); S[jj*SSTR + r0 + 2] = f.x; S[jj*SSTR + r0 + 3]     = f.y;
            f = unpk(a10); S[(jj+1)*SSTR + r0]     = f.x; S[(jj+1)*SSTR + r0 + 1] = f.y;
            f = unpk(a11); S[(jj+1)*SSTR + r0 + 2] = f.x; S[(jj+1)*SSTR + r0 + 3] = f.y;
        }
        __syncthreads();

        // ---- phase 2: online softmax update ----
        {
            float tm = -1e30f;
            #pragma unroll
            for (int j = sub; j < TJ; j += 8) tm = fmaxf(tm, S[j*SSTR + row]);
            #pragma unroll
            for (int w = 4; w >= 1; w >>= 1) tm = fmaxf(tm, __shfl_xor_sync(0xffffffffu, tm, w));
            float newm = fmaxf(m_reg, tm);
            float cc = __expf(m_reg - newm);
            float ts = 0.f;
            #pragma unroll
            for (int j = sub; j < TJ; j += 8) {
                float e = __expf(S[j*SSTR + row] - newm);
                S[j*SSTR + row] = e;
                ts += e;
            }
            #pragma unroll
            for (int w = 4; w >= 1; w >>= 1) ts += __shfl_xor_sync(0xffffffffu, ts, w);
            s_reg = s_reg*cc + ts;
            m_reg = newm;
            if (sub == 0) cb[row] = cc;
        }
        __syncthreads();

        // ---- phase 3: rescale + accumulate p @ [V|cmv|cmvc] ----
        {
            float cc = cb[ra];
            u64 c2 = pack2(cc, cc);
            #pragma unroll
            for (int u = 0; u < 5; u++) ac[u] = mul2(ac[u], c2);
            const float* vb = vt + dg*10;
            #pragma unroll 4
            for (int j = 0; j < TJ; j++) {
                float p = S[j*SSTR + ra];
                u64 p2 = pack2(p, p);
                const float* vr = vb + j*VW;
                ac[0] = ffma2(p2, *(const u64*)(vr + 0), ac[0]);
                ac[1] = ffma2(p2, *(const u64*)(vr + 2), ac[1]);
                ac[2] = ffma2(p2, *(const u64*)(vr + 4), ac[2]);
                ac[3] = ffma2(p2, *(const u64*)(vr + 6), ac[3]);
                ac[4] = ffma2(p2, *(const u64*)(vr + 8), ac[4]);
            }
        }
        __syncthreads();
    }

    // write partials
    int slot = (sp*LDIM + l)*NIT + it;
    if (sub == 0) {
        g_mx[slot*TI + row] = m_reg;
        g_sm[slot*TI + row] = s_reg;
    }
    // g_acc layout [slot][d][row]: coalesced stores (lanes = consecutive ra)
    float* ga = &g_acc[(slot*VW + dg*10)*TI + ra];
    #pragma unroll
    for (int u = 0; u < 5; u++) {
        float2 f = unpk(ac[u]);
        ga[(u*2    )*TI] = f.x;
        ga[(u*2 + 1)*TI] = f.y;
    }
}

// ==================== Kernel B2: combine + epilogue ====================
#define STG 81   // padded stage stride (conflict-free)

__global__ __launch_bounds__(256) void combine_kernel(
    const float* __restrict__ hin, const float* __restrict__ coord,
    float* __restrict__ out)
{
    __shared__ float stage[TI*STG];
    int tid = threadIdx.x;
    int it = blockIdx.x, l = blockIdx.y;
    int ra = tid & 31, dg = tid >> 5;

    int b0 = ((0*LDIM + l)*NIT + it);
    int b1 = ((1*LDIM + l)*NIT + it);
    int b2 = ((2*LDIM + l)*NIT + it);

    float m0 = g_mx[b0*TI + ra], m1 = g_mx[b1*TI + ra], m2 = g_mx[b2*TI + ra];
    float M = fmaxf(m0, fmaxf(m1, m2));
    float w0 = __expf(m0 - M), w1 = __expf(m1 - M), w2 = __expf(m2 - M);
    float denom = g_sm[b0*TI + ra]*w0 + g_sm[b1*TI + ra]*w1 + g_sm[b2*TI + ra]*w2;
    float inv = 1.f / denom;

    const float* a0 = &g_acc[(b0*VW + dg*10)*TI + ra];
    const float* a1 = &g_acc[(b1*VW + dg*10)*TI + ra];
    const float* a2 = &g_acc[(b2*VW + dg*10)*TI + ra];
    float* st = &stage[ra*STG + dg*10];
    #pragma unroll
    for (int u = 0; u < 10; u++)
        st[u] = (a0[u*TI]*w0 + a1[u*TI]*w1 + a2[u*TI]*w2) * inv;
    __syncthreads();

    // h output with residual
    {
        int r = tid >> 3, c0 = (tid & 7) * 8;
        int gi = ((it*TI + r)*LDIM + l)*HDIM + c0;
        const float* sg = &stage[r*STG + c0];
        float4 h0 = *(const float4*)&hin[gi];
        float4 h1 = *(const float4*)&hin[gi + 4];
        *(float4*)&out[gi] =
            make_float4(h0.x + sg[0], h0.y + sg[1], h0.z + sg[2], h0.w + sg[3]);
        *(float4*)&out[gi + 4] =
            make_float4(h1.x + sg[4], h1.y + sg[5], h1.z + sg[6], h1.w + sg[7]);
    }
    // coord output: out = coord*(1+S1[k]) - S2[k][t]
    for (int e = tid; e < TI*12; e += 256) {
        int r = e / 12, idx = e % 12, k = idx / 3;
        float S1 = stage[r*STG + 64 + k];
        float S2 = stage[r*STG + 68 + idx];
        int off = ((it*TI + r)*LDIM + l)*12 + idx;
        out[COUT_OFF + off] = coord[off] * (1.f + S1) - S2;
    }
}

// ==================== launch ====================
extern "C" void kernel_launch(void* const* d_in, const int* in_sizes, int n_in,
                              void* d_out, int out_size) {
    const float* h     = (const float*)d_in[0];
    const float* coord = (const float*)d_in[1];
    const float* wq1 = (const float*)d_in[2];
    const float* bq1 = (const float*)d_in[3];
    const float* wq2 = (const float*)d_in[4];
    const float* bq2 = (const float*)d_in[5];
    const float* wk1 = (const float*)d_in[6];
    const float* bk1 = (const float*)d_in[7];
    const float* wk2 = (const float*)d_in[8];
    const float* bk2 = (const float*)d_in[9];
    const float* wv1 = (const float*)d_in[10];
    const float* bv1 = (const float*)d_in[11];
    const float* wv2 = (const float*)d_in[12];
    const float* bv2 = (const float*)d_in[13];
    const float* wc1 = (const float*)d_in[14];
    const float* bc1 = (const float*)d_in[15];
    const float* wc2 = (const float*)d_in[16];
    float* out = (float*)d_out;

    mlp_kernel<<<dim3(NROWS/32, 3), 256>>>(h, coord, wq1, bq1, wq2, bq2,
                                           wk1, bk1, wk2, bk2, wv1, bv1, wv2, bv2,
                                           wc1, bc1, wc2);

    cudaFuncSetAttribute(attn_part_kernel, cudaFuncAttributeMaxDynamicSharedMemorySize, B1_BYTES);
    attn_part_kernel<<<dim3(NIT, LDIM, JSPLIT), 256, B1_BYTES>>>();

    combine_kernel<<<dim3(NIT, LDIM), 256>>>(h, coord, out);
}

// round 6
// speedup vs baseline: 2.5993x; 1.3579x over previous
#include <cuda_runtime.h>

#define NTOK 768
#define LDIM 8
#define HDIM 64
#define NROWS (NTOK*LDIM)          // 6144
#define HOUT_ELEMS (NROWS*HDIM)    // 393216
#define COUT_OFF HOUT_ELEMS

#define TI 32
#define TJ 64
#define JSPLIT 3
#define TPS 4                      // tiles per split (12 total / 3)
#define NIT (NTOK/TI)              // 24
#define SLOTS (NIT*LDIM*JSPLIT)    // 576
#define VW 80

// -------- scratch (no allocations allowed) --------
__device__ float g_q[NROWS*HDIM];
__device__ float g_k[NROWS*HDIM];
__device__ float g_v[NROWS*HDIM];
__device__ float g_cmv[NROWS*4];
__device__ float g_cmvc[NROWS*12];
__device__ float g_acc[SLOTS*VW*TI];   // [slot][d][row] for coalescing
__device__ float g_mx[SLOTS*TI];
__device__ float g_sm[SLOTS*TI];

using u64 = unsigned long long;

__device__ __forceinline__ u64 ffma2(u64 a, u64 b, u64 c) {
    u64 d; asm("fma.rn.f32x2 %0, %1, %2, %3;" : "=l"(d) : "l"(a), "l"(b), "l"(c)); return d;
}
__device__ __forceinline__ u64 mul2(u64 a, u64 b) {
    u64 d; asm("mul.rn.f32x2 %0, %1, %2;" : "=l"(d) : "l"(a), "l"(b)); return d;
}
__device__ __forceinline__ u64 pack2(float x, float y) {
    u64 r; asm("mov.b64 %0, {%1, %2};" : "=l"(r) : "f"(x), "f"(y)); return r;
}
__device__ __forceinline__ float2 unpk(u64 v) {
    float2 f; asm("mov.b64 {%0, %1}, %2;" : "=f"(f.x), "=f"(f.y) : "l"(v)); return f;
}

// ==================== Kernel A: MLPs v2 (4 rows/thread, padded W) ====================
#define MROWS 128
#define AST 72     // activation row stride: 64 cols + 4-pad after col 32 + 4 tail
#define WST 68     // weight row stride: 64 outs + 4-pad after out 32

// mlp smem layout (floats)
#define M_BUFA 0
#define M_BUFB (MROWS*AST)            // 9216
#define M_W    (2*MROWS*AST)          // 18432
#define M_FLOATS (M_W + 64*WST)       // 22784
#define M_BYTES (M_FLOATS*4)          // 91136

// store W[c][o] at c*WST + o + (o>=32 ? 4 : 0)
__device__ __forceinline__ void load_wpad(const float* __restrict__ wg, float* sW, int tid) {
    #pragma unroll
    for (int i = 0; i < 4; i++) {
        int idx = tid + i*256;               // float4 index 0..1023
        float4 v = ((const float4*)wg)[idx];
        int c = idx >> 4;
        int o = (idx & 15) * 4;
        *(float4*)&sW[c*WST + o + (o >= 32 ? 4 : 0)] = v;
    }
}

// one 64->64 layer + ReLU for 4 rows per thread.
// outs: padded smem output (or null). outg: gmem output base (or null).
__device__ __forceinline__ void layerv2(const float* __restrict__ in, const float* __restrict__ sW,
                                        const float* __restrict__ bg,
                                        float* outs, float* outg,
                                        int r, int o0, int wof, int row0) {
    float4 b0 = *(const float4*)&bg[o0];
    float4 b1 = *(const float4*)&bg[o0 + 4];
    u64 acc[4][4];
    #pragma unroll
    for (int k = 0; k < 4; k++) {
        acc[k][0] = pack2(b0.x, b0.y); acc[k][1] = pack2(b0.z, b0.w);
        acc[k][2] = pack2(b1.x, b1.y); acc[k][3] = pack2(b1.z, b1.w);
    }
    const float* in0 = in + r*AST;
    #pragma unroll
    for (int half = 0; half < 2; half++) {
        int coff = half * 36;                    // activation padded offset
        const float* wrow = sW + half*32*WST + wof;
        const float* ip = in0 + coff;
        #pragma unroll 8
        for (int c2 = 0; c2 < 32; c2++) {
            float h0 = ip[c2];
            float h1 = ip[32*AST + c2];
            float h2 = ip[64*AST + c2];
            float h3 = ip[96*AST + c2];
            ulonglong2 wa = *(const ulonglong2*)(wrow + c2*WST);
            ulonglong2 wb = *(const ulonglong2*)(wrow + c2*WST + 4);
            u64 hh;
            hh = pack2(h0, h0);
            acc[0][0] = ffma2(hh, wa.x, acc[0][0]); acc[0][1] = ffma2(hh, wa.y, acc[0][1]);
            acc[0][2] = ffma2(hh, wb.x, acc[0][2]); acc[0][3] = ffma2(hh, wb.y, acc[0][3]);
            hh = pack2(h1, h1);
            acc[1][0] = ffma2(hh, wa.x, acc[1][0]); acc[1][1] = ffma2(hh, wa.y, acc[1][1]);
            acc[1][2] = ffma2(hh, wb.x, acc[1][2]); acc[1][3] = ffma2(hh, wb.y, acc[1][3]);
            hh = pack2(h2, h2);
            acc[2][0] = ffma2(hh, wa.x, acc[2][0]); acc[2][1] = ffma2(hh, wa.y, acc[2][1]);
            acc[2][2] = ffma2(hh, wb.x, acc[2][2]); acc[2][3] = ffma2(hh, wb.y, acc[2][3]);
            hh = pack2(h3, h3);
            acc[3][0] = ffma2(hh, wa.x, acc[3][0]); acc[3][1] = ffma2(hh, wa.y, acc[3][1]);
            acc[3][2] = ffma2(hh, wb.x, acc[3][2]); acc[3][3] = ffma2(hh, wb.y, acc[3][3]);
        }
    }
    #pragma unroll
    for (int k = 0; k < 4; k++) {
        float2 f0 = unpk(acc[k][0]), f1 = unpk(acc[k][1]);
        float2 f2 = unpk(acc[k][2]), f3 = unpk(acc[k][3]);
        float4 lo = make_float4(fmaxf(f0.x,0.f), fmaxf(f0.y,0.f), fmaxf(f1.x,0.f), fmaxf(f1.y,0.f));
        float4 hi = make_float4(fmaxf(f2.x,0.f), fmaxf(f2.y,0.f), fmaxf(f3.x,0.f), fmaxf(f3.y,0.f));
        int rr = r + 32*k;
        if (outs) {
            float* d = &outs[rr*AST + wof];
            *(float4*)d = lo; *(float4*)(d + 4) = hi;
        }
        if (outg) {
            float* d = &outg[(row0 + rr)*HDIM + o0];
            *(float4*)d = lo; *(float4*)(d + 4) = hi;
        }
    }
}

__global__ __launch_bounds__(256) void mlp_kernel(
    const float* __restrict__ h, const float* __restrict__ coord,
    const float* __restrict__ wq1, const float* __restrict__ bq1,
    const float* __restrict__ wq2, const float* __restrict__ bq2,
    const float* __restrict__ wk1, const float* __restrict__ bk1,
    const float* __restrict__ wk2, const float* __restrict__ bk2,
    const float* __restrict__ wv1, const float* __restrict__ bv1,
    const float* __restrict__ wv2, const float* __restrict__ bv2,
    const float* __restrict__ wc1, const float* __restrict__ bc1,
    const float* __restrict__ wc2)
{
    extern __shared__ float sm[];
    float* bufA = sm + M_BUFA;
    float* bufB = sm + M_BUFB;
    float* sW   = sm + M_W;

    int tid = threadIdx.x;
    int row0 = blockIdx.x * MROWS;
    int chain = blockIdx.y;
    int r = tid >> 3;                 // 0..31
    int o0 = (tid & 7) * 8;
    int wof = o0 + (o0 >= 32 ? 4 : 0);

    // load h tile (128 x 64) into padded bufA
    #pragma unroll
    for (int k = 0; k < 4; k++) {
        int rr = r + 32*k;
        const float4* src = (const float4*)&h[(row0 + rr)*HDIM + o0];
        float4 a = src[0], b = src[1];
        float* dst = &bufA[rr*AST + wof];
        *(float4*)dst = a; *(float4*)(dst + 4) = b;
    }

    const float *w1, *b1, *w2, *b2;
    float* gout;
    if (chain == 0)      { w1 = wq1; b1 = bq1; w2 = wq2; b2 = bq2; gout = g_q; }
    else if (chain == 1) { w1 = wk1; b1 = bk1; w2 = wk2; b2 = bk2; gout = g_k; }
    else                 { w1 = wv1; b1 = bv1; w2 = wv2; b2 = bv2; gout = g_v; }

    load_wpad(w1, sW, tid);
    __syncthreads();
    layerv2(bufA, sW, b1, bufB, (float*)0, r, o0, wof, row0);
    __syncthreads();
    load_wpad(w2, sW, tid);
    __syncthreads();
    layerv2(bufB, sW, b2, (chain == 2 ? bufA : (float*)0), gout, r, o0, wof, row0);

    if (chain == 2) {
        __syncthreads();
        load_wpad(wc1, sW, tid);
        __syncthreads();
        layerv2(bufA, sW, bc1, bufB, (float*)0, r, o0, wof, row0);
        __syncthreads();
        if (tid < 64) ((float4*)sW)[tid] = ((const float4*)wc2)[tid];
        __syncthreads();
        // final: cmv = hidden @ wc2 (64 -> 4), 2 outputs per thread
        {
            int rr = tid >> 1;            // 0..127
            int ob = (tid & 1) * 2;
            float a0 = 0.f, a1 = 0.f;
            const float* inr = &bufB[rr*AST];
            #pragma unroll 8
            for (int c = 0; c < 32; c++) {
                float x = inr[c];
                a0 += x * sW[c*4 + ob];
                a1 += x * sW[c*4 + ob + 1];
            }
            #pragma unroll 8
            for (int c = 32; c < 64; c++) {
                float x = inr[c + 4];
                a0 += x * sW[c*4 + ob];
                a1 += x * sW[c*4 + ob + 1];
            }
            int row = row0 + rr;
            g_cmv[row*4 + ob]     = a0;
            g_cmv[row*4 + ob + 1] = a1;
            #pragma unroll
            for (int t = 0; t < 3; t++) {
                g_cmvc[row*12 + ob*3 + t]     = a0 * coord[row*12 + ob*3 + t];
                g_cmvc[row*12 + (ob+1)*3 + t] = a1 * coord[row*12 + (ob+1)*3 + t];
            }
        }
    }
}

// ==================== Kernel B1: flash attention partials ====================
#define KSTR 68   // multiple of 4: float4 row stores stay 16B-aligned
#define SSTR 33

#define OQT 0
#define OK  2048                    // 64 cols x 32 rows
#define OV  (OK + TJ*KSTR)          // 6400
#define OS  (OV + TJ*VW)            // 11520
#define OC  (OS + TJ*SSTR)          // 13632
#define B1_FLOATS (OC + TI)         // 13664
#define B1_BYTES (B1_FLOATS*4)      // 54656

__global__ __launch_bounds__(256, 4) void attn_part_kernel()
{
    extern __shared__ float smf[];
    float* qT = smf + OQT;
    float* kp = smf + OK;
    float* vt = smf + OV;
    float* S  = smf + OS;
    float* cb = smf + OC;

    int tid = threadIdx.x;
    int it = blockIdx.x, l = blockIdx.y, sp = blockIdx.z;
    int i0 = it * TI;
    int j0 = sp * (TPS*TJ);

    // load q tile transposed: qT[c][r]
    {
        int r = tid >> 3, c0 = (tid & 7) * 8;
        const float* src = &g_q[((i0 + r)*LDIM + l)*HDIM + c0];
        float4 a = *(const float4*)src;
        float4 b = *(const float4*)(src + 4);
        float v8[8] = {a.x, a.y, a.z, a.w, b.x, b.y, b.z, b.w};
        #pragma unroll
        for (int u = 0; u < 8; u++) qT[(c0 + u)*TI + r] = v8[u];
    }

    int rg = tid & 7, jg = tid >> 3, r0 = rg * 4, jj = jg * 2;  // phase1 roles
    int row = tid >> 3, sub = tid & 7;                          // phase2 roles
    int ra = tid & 31, dg = tid >> 5;                           // phase3 roles
    int cbase = (dg < 4) ? dg*12 : 48 + (dg - 4)*8;             // 16B-aligned chunks

    float m_reg = -1e30f, s_reg = 0.f;
    u64 ac[6] = {0, 0, 0, 0, 0, 0};

    for (int t = 0; t < TPS; t++) {
        int jb = j0 + t*TJ;
        // load K tile (64 x 64, padded stride 68)
        {
            int j = tid >> 2, c0 = (tid & 3) * 16;
            const float* src = &g_k[((jb + j)*LDIM + l)*HDIM + c0];
            float* d = &kp[j*KSTR + c0];
            #pragma unroll
            for (int q4 = 0; q4 < 4; q4++)
                *(float4*)(d + q4*4) = *(const float4*)(src + q4*4);
        }
        // load V fused tile (64 x 80): [v(64)|cmv(4)|cmvc(12)]
        {
            int j = tid >> 2, c0 = (tid & 3) * 16;
            const float* src = &g_v[((jb + j)*LDIM + l)*HDIM + c0];
            float* d = &vt[j*VW + c0];
            #pragma unroll
            for (int q4 = 0; q4 < 4; q4++)
                *(float4*)(d + q4*4) = *(const float4*)(src + q4*4);
        }
        if (tid < TJ) {
            int grow = (jb + tid)*LDIM + l;
            *(float4*)&vt[tid*VW + 64] = *(const float4*)&g_cmv[grow*4];
            const float* cc = &g_cmvc[grow*12];
            *(float4*)&vt[tid*VW + 68] = *(const float4*)cc;
            *(float4*)&vt[tid*VW + 72] = *(const float4*)(cc + 4);
            *(float4*)&vt[tid*VW + 76] = *(const float4*)(cc + 8);
        }
        __syncthreads();

        // ---- phase 1: scores -> S[j][r] (transposed) ----
        {
            u64 a00 = 0, a01 = 0, a10 = 0, a11 = 0;
            const float* kr0 = &kp[jj*KSTR];
            const float* kr1 = &kp[(jj + 1)*KSTR];
            #pragma unroll 8
            for (int c = 0; c < 64; c++) {
                u64 q01 = *(const u64*)&qT[c*TI + r0];
                u64 q23 = *(const u64*)&qT[c*TI + r0 + 2];
                float k0v = kr0[c], k1v = kr1[c];
                u64 k0 = pack2(k0v, k0v);
                u64 k1 = pack2(k1v, k1v);
                a00 = ffma2(q01, k0, a00);
                a01 = ffma2(q23, k0, a01);
                a10 = ffma2(q01, k1, a10);
                a11 = ffma2(q23, k1, a11);
            }
            float2 f;
            f = unpk(a00); S[jj*SSTR + r0]     = f.x; S[jj*SSTR + r0 + 1]     = f.y;
            f = unpk(a01); S[jj*SSTR + r0 + 2] = f.x; S[jj*SSTR + r0 + 3]     = f.y;
            f = unpk(a10); S[(jj+1)*SSTR + r0]     = f.x; S[(jj+1)*SSTR + r0 + 1] = f.y;
            f = unpk(a11); S[(jj+1)*SSTR + r0 + 2] = f.x; S[(jj+1)*SSTR + r0 + 3] = f.y;
        }
        __syncthreads();

        // ---- phase 2: online softmax update ----
        {
            float tm = -1e30f;
            #pragma unroll
            for (int j = sub; j < TJ; j += 8) tm = fmaxf(tm, S[j*SSTR + row]);
            #pragma unroll
            for (int w = 4; w >= 1; w >>= 1) tm = fmaxf(tm, __shfl_xor_sync(0xffffffffu, tm, w));
            float newm = fmaxf(m_reg, tm);
            float cc = __expf(m_reg - newm);
            float ts = 0.f;
            #pragma unroll
            for (int j = sub; j < TJ; j += 8) {
                float e = __expf(S[j*SSTR + row] - newm);
                S[j*SSTR + row] = e;
                ts += e;
            }
            #pragma unroll
            for (int w = 4; w >= 1; w >>= 1) ts += __shfl_xor_sync(0xffffffffu, ts, w);
            s_reg = s_reg*cc + ts;
            m_reg = newm;
            if (sub == 0) cb[row] = cc;
        }
        __syncthreads();

        // ---- phase 3: rescale + accumulate p @ [V|cmv|cmvc] ----
        {
            float cc = cb[ra];
            u64 c2 = pack2(cc, cc);
            const float* vb = vt + cbase;
            if (dg < 4) {
                #pragma unroll
                for (int u = 0; u < 6; u++) ac[u] = mul2(ac[u], c2);
                #pragma unroll 4
                for (int j = 0; j < TJ; j++) {
                    float p = S[j*SSTR + ra];
                    u64 p2 = pack2(p, p);
                    const float* vr = vb + j*VW;
                    ulonglong2 v01 = *(const ulonglong2*)(vr);
                    ulonglong2 v23 = *(const ulonglong2*)(vr + 4);
                    ulonglong2 v45 = *(const ulonglong2*)(vr + 8);
                    ac[0] = ffma2(p2, v01.x, ac[0]);
                    ac[1] = ffma2(p2, v01.y, ac[1]);
                    ac[2] = ffma2(p2, v23.x, ac[2]);
                    ac[3] = ffma2(p2, v23.y, ac[3]);
                    ac[4] = ffma2(p2, v45.x, ac[4]);
                    ac[5] = ffma2(p2, v45.y, ac[5]);
                }
            } else {
                #pragma unroll
                for (int u = 0; u < 4; u++) ac[u] = mul2(ac[u], c2);
                #pragma unroll 4
                for (int j = 0; j < TJ; j++) {
                    float p = S[j*SSTR + ra];
                    u64 p2 = pack2(p, p);
                    const float* vr = vb + j*VW;
                    ulonglong2 v01 = *(const ulonglong2*)(vr);
                    ulonglong2 v23 = *(const ulonglong2*)(vr + 4);
                    ac[0] = ffma2(p2, v01.x, ac[0]);
                    ac[1] = ffma2(p2, v01.y, ac[1]);
                    ac[2] = ffma2(p2, v23.x, ac[2]);
                    ac[3] = ffma2(p2, v23.y, ac[3]);
                }
            }
        }
        __syncthreads();
    }

    // write partials
    int slot = (sp*LDIM + l)*NIT + it;
    if (sub == 0) {
        g_mx[slot*TI + row] = m_reg;
        g_sm[slot*TI + row] = s_reg;
    }
    // g_acc layout [slot][d][row]: coalesced stores (lanes = consecutive ra)
    {
        float* ga = &g_acc[(slot*VW + cbase)*TI + ra];
        if (dg < 4) {
            #pragma unroll
            for (int u = 0; u < 6; u++) {
                float2 f = unpk(ac[u]);
                ga[(u*2    )*TI] = f.x;
                ga[(u*2 + 1)*TI] = f.y;
            }
        } else {
            #pragma unroll
            for (int u = 0; u < 4; u++) {
                float2 f = unpk(ac[u]);
                ga[(u*2    )*TI] = f.x;
                ga[(u*2 + 1)*TI] = f.y;
            }
        }
    }
}

// ==================== Kernel B2: combine + epilogue ====================
#define STG 81   // padded stage stride (conflict-free)

__global__ __launch_bounds__(256) void combine_kernel(
    const float* __restrict__ hin, const float* __restrict__ coord,
    float* __restrict__ out)
{
    __shared__ float stage[TI*STG];
    int tid = threadIdx.x;
    int it = blockIdx.x, l = blockIdx.y;
    int ra = tid & 31, dg = tid >> 5;

    int b0 = ((0*LDIM + l)*NIT + it);
    int b1 = ((1*LDIM + l)*NIT + it);
    int b2 = ((2*LDIM + l)*NIT + it);

    float m0 = g_mx[b0*TI + ra], m1 = g_mx[b1*TI + ra], m2 = g_mx[b2*TI + ra];
    float M = fmaxf(m0, fmaxf(m1, m2));
    float w0 = __expf(m0 - M), w1 = __expf(m1 - M), w2 = __expf(m2 - M);
    float denom = g_sm[b0*TI + ra]*w0 + g_sm[b1*TI + ra]*w1 + g_sm[b2*TI + ra]*w2;
    float inv = 1.f / denom;

    const float* a0 = &g_acc[(b0*VW + dg*10)*TI + ra];
    const float* a1 = &g_acc[(b1*VW + dg*10)*TI + ra];
    const float* a2 = &g_acc[(b2*VW + dg*10)*TI + ra];
    float* st = &stage[ra*STG + dg*10];
    #pragma unroll
    for (int u = 0; u < 10; u++)
        st[u] = (a0[u*TI]*w0 + a1[u*TI]*w1 + a2[u*TI]*w2) * inv;
    __syncthreads();

    // h output with residual
    {
        int r = tid >> 3, c0 = (tid & 7) * 8;
        int gi = ((it*TI + r)*LDIM + l)*HDIM + c0;
        const float* sg = &stage[r*STG + c0];
        float4 h0 = *(const float4*)&hin[gi];
        float4 h1 = *(const float4*)&hin[gi + 4];
        *(float4*)&out[gi] =
            make_float4(h0.x + sg[0], h0.y + sg[1], h0.z + sg[2], h0.w + sg[3]);
        *(float4*)&out[gi + 4] =
            make_float4(h1.x + sg[4], h1.y + sg[5], h1.z + sg[6], h1.w + sg[7]);
    }
    // coord output: out = coord*(1+S1[k]) - S2[k][t]
    for (int e = tid; e < TI*12; e += 256) {
        int r = e / 12, idx = e % 12, k = idx / 3;
        float S1 = stage[r*STG + 64 + k];
        float S2 = stage[r*STG + 68 + idx];
        int off = ((it*TI + r)*LDIM + l)*12 + idx;
        out[COUT_OFF + off] = coord[off] * (1.f + S1) - S2;
    }
}

// ==================== launch ====================
extern "C" void kernel_launch(void* const* d_in, const int* in_sizes, int n_in,
                              void* d_out, int out_size) {
    const float* h     = (const float*)d_in[0];
    const float* coord = (const float*)d_in[1];
    const float* wq1 = (const float*)d_in[2];
    const float* bq1 = (const float*)d_in[3];
    const float* wq2 = (const float*)d_in[4];
    const float* bq2 = (const float*)d_in[5];
    const float* wk1 = (const float*)d_in[6];
    const float* bk1 = (const float*)d_in[7];
    const float* wk2 = (const float*)d_in[8];
    const float* bk2 = (const float*)d_in[9];
    const float* wv1 = (const float*)d_in[10];
    const float* bv1 = (const float*)d_in[11];
    const float* wv2 = (const float*)d_in[12];
    const float* bv2 = (const float*)d_in[13];
    const float* wc1 = (const float*)d_in[14];
    const float* bc1 = (const float*)d_in[15];
    const float* wc2 = (const float*)d_in[16];
    float* out = (float*)d_out;

    cudaFuncSetAttribute(mlp_kernel, cudaFuncAttributeMaxDynamicSharedMemorySize, M_BYTES);
    mlp_kernel<<<dim3(NROWS/MROWS, 3), 256, M_BYTES>>>(h, coord, wq1, bq1, wq2, bq2,
                                                       wk1, bk1, wk2, bk2, wv1, bv1, wv2, bv2,
                                                       wc1, bc1, wc2);

    cudaFuncSetAttribute(attn_part_kernel, cudaFuncAttributeMaxDynamicSharedMemorySize, B1_BYTES);
    attn_part_kernel<<<dim3(NIT, LDIM, JSPLIT), 256, B1_BYTES>>>();

    combine_kernel<<<dim3(NIT, LDIM), 256>>>(h, coord, out);
}

// round 7
// speedup vs baseline: 2.8521x; 1.0973x over previous
#include <cuda_runtime.h>
#include <cstdint>

#define NTOK 768
#define LDIM 8
#define HDIM 64
#define NROWS (NTOK*LDIM)          // 6144
#define HOUT_ELEMS (NROWS*HDIM)    // 393216
#define COUT_OFF HOUT_ELEMS

#define TI 32
#define TJ 64
#define JSPLIT 3
#define TPS 4                      // tiles per split (12 total / 3)
#define NIT (NTOK/TI)              // 24
#define SLOTS (NIT*LDIM*JSPLIT)    // 576
#define VW 80

// -------- scratch (no allocations allowed) --------
__device__ float g_q[NROWS*HDIM];
__device__ float g_k[NROWS*HDIM];
__device__ float g_v[NROWS*HDIM];
__device__ float g_cmv[NROWS*4];
__device__ float g_cmvc[NROWS*12];
__device__ float g_acc[SLOTS*VW*TI];   // [slot][d][row] for coalescing
__device__ float g_mx[SLOTS*TI];
__device__ float g_sm[SLOTS*TI];

using u64 = unsigned long long;

__device__ __forceinline__ u64 ffma2(u64 a, u64 b, u64 c) {
    u64 d; asm("fma.rn.f32x2 %0, %1, %2, %3;" : "=l"(d) : "l"(a), "l"(b), "l"(c)); return d;
}
__device__ __forceinline__ u64 mul2(u64 a, u64 b) {
    u64 d; asm("mul.rn.f32x2 %0, %1, %2;" : "=l"(d) : "l"(a), "l"(b)); return d;
}
__device__ __forceinline__ u64 pack2(float x, float y) {
    u64 r; asm("mov.b64 %0, {%1, %2};" : "=l"(r) : "f"(x), "f"(y)); return r;
}
__device__ __forceinline__ float2 unpk(u64 v) {
    float2 f; asm("mov.b64 {%0, %1}, %2;" : "=f"(f.x), "=f"(f.y) : "l"(v)); return f;
}

__device__ __forceinline__ void cp16(uint32_t s, const void* g) {
    asm volatile("cp.async.cg.shared.global [%0], [%1], 16;" :: "r"(s), "l"(g));
}
#define CP_COMMIT() asm volatile("cp.async.commit_group;" ::: "memory")
#define CP_WAIT(n)  asm volatile("cp.async.wait_group %0;" :: "n"(n) : "memory")

// ==================== Kernel A: MLPs v3 (512 thr, 2 rows/thread) ====================
#define MROWS 128
#define MTHR 512
#define AST 72     // activation row stride: 64 cols + 4-pad after col 32 + 4 tail
#define WST 68     // weight row stride: 64 outs + 4-pad after out 32

// mlp smem layout (floats)
#define M_BUFA 0
#define M_BUFB (MROWS*AST)            // 9216
#define M_W    (2*MROWS*AST)          // 18432
#define M_FLOATS (M_W + 64*WST)       // 22784
#define M_BYTES (M_FLOATS*4)          // 91136

// store W[c][o] at c*WST + o + (o>=32 ? 4 : 0)
__device__ __forceinline__ void load_wpad(const float* __restrict__ wg, float* sW, int tid) {
    #pragma unroll
    for (int i = 0; i < 2; i++) {
        int idx = tid + i*MTHR;              // float4 index 0..1023
        float4 v = ((const float4*)wg)[idx];
        int c = idx >> 4;
        int o = (idx & 15) * 4;
        *(float4*)&sW[c*WST + o + (o >= 32 ? 4 : 0)] = v;
    }
}

// one 64->64 layer + ReLU for 2 rows per thread (rows r, r+64).
__device__ __forceinline__ void layer2r(const float* __restrict__ in, const float* __restrict__ sW,
                                        const float* __restrict__ bg,
                                        float* outs, float* outg,
                                        int r, int o0, int wof, int row0) {
    float4 b0 = *(const float4*)&bg[o0];
    float4 b1 = *(const float4*)&bg[o0 + 4];
    u64 acc[2][4];
    #pragma unroll
    for (int k = 0; k < 2; k++) {
        acc[k][0] = pack2(b0.x, b0.y); acc[k][1] = pack2(b0.z, b0.w);
        acc[k][2] = pack2(b1.x, b1.y); acc[k][3] = pack2(b1.z, b1.w);
    }
    const float* in0 = in + r*AST;
    #pragma unroll
    for (int half = 0; half < 2; half++) {
        int coff = half * 36;                    // activation padded offset
        const float* wrow = sW + half*32*WST + wof;
        const float* ip = in0 + coff;
        #pragma unroll 8
        for (int c2 = 0; c2 < 32; c2++) {
            float h0 = ip[c2];
            float h1 = ip[64*AST + c2];
            ulonglong2 wa = *(const ulonglong2*)(wrow + c2*WST);
            ulonglong2 wb = *(const ulonglong2*)(wrow + c2*WST + 4);
            u64 hh;
            hh = pack2(h0, h0);
            acc[0][0] = ffma2(hh, wa.x, acc[0][0]); acc[0][1] = ffma2(hh, wa.y, acc[0][1]);
            acc[0][2] = ffma2(hh, wb.x, acc[0][2]); acc[0][3] = ffma2(hh, wb.y, acc[0][3]);
            hh = pack2(h1, h1);
            acc[1][0] = ffma2(hh, wa.x, acc[1][0]); acc[1][1] = ffma2(hh, wa.y, acc[1][1]);
            acc[1][2] = ffma2(hh, wb.x, acc[1][2]); acc[1][3] = ffma2(hh, wb.y, acc[1][3]);
        }
    }
    #pragma unroll
    for (int k = 0; k < 2; k++) {
        float2 f0 = unpk(acc[k][0]), f1 = unpk(acc[k][1]);
        float2 f2 = unpk(acc[k][2]), f3 = unpk(acc[k][3]);
        float4 lo = make_float4(fmaxf(f0.x,0.f), fmaxf(f0.y,0.f), fmaxf(f1.x,0.f), fmaxf(f1.y,0.f));
        float4 hi = make_float4(fmaxf(f2.x,0.f), fmaxf(f2.y,0.f), fmaxf(f3.x,0.f), fmaxf(f3.y,0.f));
        int rr = r + 64*k;
        if (outs) {
            float* d = &outs[rr*AST + wof];
            *(float4*)d = lo; *(float4*)(d + 4) = hi;
        }
        if (outg) {
            float* d = &outg[(row0 + rr)*HDIM + o0];
            *(float4*)d = lo; *(float4*)(d + 4) = hi;
        }
    }
}

__global__ __launch_bounds__(MTHR) void mlp_kernel(
    const float* __restrict__ h, const float* __restrict__ coord,
    const float* __restrict__ wq1, const float* __restrict__ bq1,
    const float* __restrict__ wq2, const float* __restrict__ bq2,
    const float* __restrict__ wk1, const float* __restrict__ bk1,
    const float* __restrict__ wk2, const float* __restrict__ bk2,
    const float* __restrict__ wv1, const float* __restrict__ bv1,
    const float* __restrict__ wv2, const float* __restrict__ bv2,
    const float* __restrict__ wc1, const float* __restrict__ bc1,
    const float* __restrict__ wc2)
{
    extern __shared__ float sm[];
    float* bufA = sm + M_BUFA;
    float* bufB = sm + M_BUFB;
    float* sW   = sm + M_W;

    int tid = threadIdx.x;
    int row0 = blockIdx.x * MROWS;
    int chain = blockIdx.y;
    int r = tid >> 3;                 // 0..63
    int o0 = (tid & 7) * 8;
    int wof = o0 + (o0 >= 32 ? 4 : 0);

    // load h tile (128 x 64) into padded bufA, 2 rows/thread
    #pragma unroll
    for (int k = 0; k < 2; k++) {
        int rr = r + 64*k;
        const float4* src = (const float4*)&h[(row0 + rr)*HDIM + o0];
        float4 a = src[0], b = src[1];
        float* dst = &bufA[rr*AST + wof];
        *(float4*)dst = a; *(float4*)(dst + 4) = b;
    }

    const float *w1, *b1, *w2, *b2;
    float* gout;
    if (chain == 0)      { w1 = wq1; b1 = bq1; w2 = wq2; b2 = bq2; gout = g_q; }
    else if (chain == 1) { w1 = wk1; b1 = bk1; w2 = wk2; b2 = bk2; gout = g_k; }
    else                 { w1 = wv1; b1 = bv1; w2 = wv2; b2 = bv2; gout = g_v; }

    load_wpad(w1, sW, tid);
    __syncthreads();
    layer2r(bufA, sW, b1, bufB, (float*)0, r, o0, wof, row0);
    __syncthreads();
    load_wpad(w2, sW, tid);
    __syncthreads();
    layer2r(bufB, sW, b2, (chain == 2 ? bufA : (float*)0), gout, r, o0, wof, row0);

    if (chain == 2) {
        __syncthreads();
        load_wpad(wc1, sW, tid);
        __syncthreads();
        layer2r(bufA, sW, bc1, bufB, (float*)0, r, o0, wof, row0);
        __syncthreads();
        if (tid < 64) ((float4*)sW)[tid] = ((const float4*)wc2)[tid];
        __syncthreads();
        // final: cmv = hidden @ wc2 (64 -> 4), 2 outputs per thread, 256 threads
        if (tid < 256) {
            int rr = tid >> 1;            // 0..127
            int ob = (tid & 1) * 2;
            float a0 = 0.f, a1 = 0.f;
            const float* inr = &bufB[rr*AST];
            #pragma unroll 8
            for (int c = 0; c < 32; c++) {
                float x = inr[c];
                a0 += x * sW[c*4 + ob];
                a1 += x * sW[c*4 + ob + 1];
            }
            #pragma unroll 8
            for (int c = 32; c < 64; c++) {
                float x = inr[c + 4];
                a0 += x * sW[c*4 + ob];
                a1 += x * sW[c*4 + ob + 1];
            }
            int row = row0 + rr;
            g_cmv[row*4 + ob]     = a0;
            g_cmv[row*4 + ob + 1] = a1;
            #pragma unroll
            for (int t = 0; t < 3; t++) {
                g_cmvc[row*12 + ob*3 + t]     = a0 * coord[row*12 + ob*3 + t];
                g_cmvc[row*12 + (ob+1)*3 + t] = a1 * coord[row*12 + (ob+1)*3 + t];
            }
        }
    }
}

// ==================== Kernel B1: flash attention partials (cp.async pipelined) ====================
#define KSTR 68   // multiple of 4: 16B alignment for float4/cp.async
#define SSTR 33

#define OQT 0
#define OK  2048                    // 64 cols x 32 rows
#define OV  (OK + TJ*KSTR)          // 6400
#define OS  (OV + TJ*VW)            // 11520
#define OC  (OS + TJ*SSTR)          // 13632
#define B1_FLOATS (OC + TI)         // 13664
#define B1_BYTES (B1_FLOATS*4)      // 54656

__device__ __forceinline__ void issue_k_tile(uint32_t kp_s, int jb, int l, int tid) {
    int j = tid >> 2, c0 = (tid & 3) * 16;
    const float* src = &g_k[((jb + j)*LDIM + l)*HDIM + c0];
    uint32_t d = kp_s + (uint32_t)(j*KSTR + c0)*4u;
    #pragma unroll
    for (int q4 = 0; q4 < 4; q4++) cp16(d + q4*16, src + q4*4);
}
__device__ __forceinline__ void issue_v_tile(uint32_t vt_s, int jb, int l, int tid) {
    int j = tid >> 2, c0 = (tid & 3) * 16;
    const float* src = &g_v[((jb + j)*LDIM + l)*HDIM + c0];
    uint32_t d = vt_s + (uint32_t)(j*VW + c0)*4u;
    #pragma unroll
    for (int q4 = 0; q4 < 4; q4++) cp16(d + q4*16, src + q4*4);
    if (tid < TJ) {
        int grow = (jb + tid)*LDIM + l;
        uint32_t dv = vt_s + (uint32_t)(tid*VW + 64)*4u;
        cp16(dv, &g_cmv[grow*4]);
        const float* cc = &g_cmvc[grow*12];
        cp16(dv + 16, cc);
        cp16(dv + 32, cc + 4);
        cp16(dv + 48, cc + 8);
    }
}

__global__ __launch_bounds__(256, 4) void attn_part_kernel()
{
    extern __shared__ float smf[];
    float* qT = smf + OQT;
    float* kp = smf + OK;
    float* vt = smf + OV;
    float* S  = smf + OS;
    float* cb = smf + OC;

    int tid = threadIdx.x;
    int it = blockIdx.x, l = blockIdx.y, sp = blockIdx.z;
    int i0 = it * TI;
    int j0 = sp * (TPS*TJ);

    uint32_t kp_s = (uint32_t)__cvta_generic_to_shared(kp);
    uint32_t vt_s = (uint32_t)__cvta_generic_to_shared(vt);

    // prologue: start async loads of tile 0
    issue_k_tile(kp_s, j0, l, tid); CP_COMMIT();
    issue_v_tile(vt_s, j0, l, tid); CP_COMMIT();

    // load q tile transposed: qT[c][r] (overlaps with async loads)
    {
        int r = tid >> 3, c0 = (tid & 7) * 8;
        const float* src = &g_q[((i0 + r)*LDIM + l)*HDIM + c0];
        float4 a = *(const float4*)src;
        float4 b = *(const float4*)(src + 4);
        float v8[8] = {a.x, a.y, a.z, a.w, b.x, b.y, b.z, b.w};
        #pragma unroll
        for (int u = 0; u < 8; u++) qT[(c0 + u)*TI + r] = v8[u];
    }

    int rg = tid & 7, jg = tid >> 3, r0 = rg * 4, jj = jg * 2;  // phase1 roles
    int row = tid >> 3, sub = tid & 7;                          // phase2 roles
    int ra = tid & 31, dg = tid >> 5;                           // phase3 roles
    int cbase = (dg < 4) ? dg*12 : 48 + (dg - 4)*8;             // 16B-aligned chunks

    float m_reg = -1e30f, s_reg = 0.f;
    u64 ac[6] = {0, 0, 0, 0, 0, 0};

    #pragma unroll
    for (int t = 0; t < TPS; t++) {
        int jb = j0 + t*TJ;

        CP_WAIT(1);            // K(t) complete (V(t) may still be in flight)
        __syncthreads();

        // ---- phase 1: scores -> S[j][r] (transposed) ----
        {
            u64 a00 = 0, a01 = 0, a10 = 0, a11 = 0;
            const float* kr0 = &kp[jj*KSTR];
            const float* kr1 = &kp[(jj + 1)*KSTR];
            #pragma unroll 8
            for (int c = 0; c < 64; c++) {
                u64 q01 = *(const u64*)&qT[c*TI + r0];
                u64 q23 = *(const u64*)&qT[c*TI + r0 + 2];
                float k0v = kr0[c], k1v = kr1[c];
                u64 k0 = pack2(k0v, k0v);
                u64 k1 = pack2(k1v, k1v);
                a00 = ffma2(q01, k0, a00);
                a01 = ffma2(q23, k0, a01);
                a10 = ffma2(q01, k1, a10);
                a11 = ffma2(q23, k1, a11);
            }
            float2 f;
            f = unpk(a00); S[jj*SSTR + r0]     = f.x; S[jj*SSTR + r0 + 1]     = f.y;
            f = unpk(a01); S[jj*SSTR + r0 + 2] = f.x; S[jj*SSTR + r0 + 3]     = f.y;
            f = unpk(a10); S[(jj+1)*SSTR + r0]     = f.x; S[(jj+1)*SSTR + r0 + 1] = f.y;
            f = unpk(a11); S[(jj+1)*SSTR + r0 + 2] = f.x; S[(jj+1)*SSTR + r0 + 3] = f.y;
        }
        __syncthreads();

        // K buffer free: prefetch K(t+1)
        if (t < TPS-1) { issue_k_tile(kp_s, jb + TJ, l, tid); CP_COMMIT(); }

        // ---- phase 2: online softmax update ----
        {
            float tm = -1e30f;
            #pragma unroll
            for (int j = sub; j < TJ; j += 8) tm = fmaxf(tm, S[j*SSTR + row]);
            #pragma unroll
            for (int w = 4; w >= 1; w >>= 1) tm = fmaxf(tm, __shfl_xor_sync(0xffffffffu, tm, w));
            float newm = fmaxf(m_reg, tm);
            float cc = __expf(m_reg - newm);
            float ts = 0.f;
            #pragma unroll
            for (int j = sub; j < TJ; j += 8) {
                float e = __expf(S[j*SSTR + row] - newm);
                S[j*SSTR + row] = e;
                ts += e;
            }
            #pragma unroll
            for (int w = 4; w >= 1; w >>= 1) ts += __shfl_xor_sync(0xffffffffu, ts, w);
            s_reg = s_reg*cc + ts;
            m_reg = newm;
            if (sub == 0) cb[row] = cc;
        }
        if (t < TPS-1) { CP_WAIT(1); } else { CP_WAIT(0); }   // V(t) complete
        __syncthreads();

        // ---- phase 3: rescale + accumulate p @ [V|cmv|cmvc] ----
        {
            float cc = cb[ra];
            u64 c2 = pack2(cc, cc);
            const float* vb = vt + cbase;
            if (dg < 4) {
                #pragma unroll
                for (int u = 0; u < 6; u++) ac[u] = mul2(ac[u], c2);
                #pragma unroll 4
                for (int j = 0; j < TJ; j++) {
                    float p = S[j*SSTR + ra];
                    u64 p2 = pack2(p, p);
                    const float* vr = vb + j*VW;
                    ulonglong2 v01 = *(const ulonglong2*)(vr);
                    ulonglong2 v23 = *(const ulonglong2*)(vr + 4);
                    ulonglong2 v45 = *(const ulonglong2*)(vr + 8);
                    ac[0] = ffma2(p2, v01.x, ac[0]);
                    ac[1] = ffma2(p2, v01.y, ac[1]);
                    ac[2] = ffma2(p2, v23.x, ac[2]);
                    ac[3] = ffma2(p2, v23.y, ac[3]);
                    ac[4] = ffma2(p2, v45.x, ac[4]);
                    ac[5] = ffma2(p2, v45.y, ac[5]);
                }
            } else {
                #pragma unroll
                for (int u = 0; u < 4; u++) ac[u] = mul2(ac[u], c2);
                #pragma unroll 4
                for (int j = 0; j < TJ; j++) {
                    float p = S[j*SSTR + ra];
                    u64 p2 = pack2(p, p);
                    const float* vr = vb + j*VW;
                    ulonglong2 v01 = *(const ulonglong2*)(vr);
                    ulonglong2 v23 = *(const ulonglong2*)(vr + 4);
                    ac[0] = ffma2(p2, v01.x, ac[0]);
                    ac[1] = ffma2(p2, v01.y, ac[1]);
                    ac[2] = ffma2(p2, v23.x, ac[2]);
                    ac[3] = ffma2(p2, v23.y, ac[3]);
                }
            }
        }
        __syncthreads();

        // V buffer free: prefetch V(t+1)
        if (t < TPS-1) { issue_v_tile(vt_s, jb + TJ, l, tid); CP_COMMIT(); }
    }

    // write partials
    int slot = (sp*LDIM + l)*NIT + it;
    if (sub == 0) {
        g_mx[slot*TI + row] = m_reg;
        g_sm[slot*TI + row] = s_reg;
    }
    // g_acc layout [slot][d][row]: coalesced stores (lanes = consecutive ra)
    {
        float* ga = &g_acc[(slot*VW + cbase)*TI + ra];
        if (dg < 4) {
            #pragma unroll
            for (int u = 0; u < 6; u++) {
                float2 f = unpk(ac[u]);
                ga[(u*2    )*TI] = f.x;
                ga[(u*2 + 1)*TI] = f.y;
            }
        } else {
            #pragma unroll
            for (int u = 0; u < 4; u++) {
                float2 f = unpk(ac[u]);
                ga[(u*2    )*TI] = f.x;
                ga[(u*2 + 1)*TI] = f.y;
            }
        }
    }
}

// ==================== Kernel B2: combine + epilogue ====================
#define STG 81   // padded stage stride (conflict-free)

__global__ __launch_bounds__(256) void combine_kernel(
    const float* __restrict__ hin, const float* __restrict__ coord,
    float* __restrict__ out)
{
    __shared__ float stage[TI*STG];
    int tid = threadIdx.x;
    int it = blockIdx.x, l = blockIdx.y;
    int ra = tid & 31, dg = tid >> 5;

    int b0 = ((0*LDIM + l)*NIT + it);
    int b1 = ((1*LDIM + l)*NIT + it);
    int b2 = ((2*LDIM + l)*NIT + it);

    float m0 = g_mx[b0*TI + ra], m1 = g_mx[b1*TI + ra], m2 = g_mx[b2*TI + ra];
    float M = fmaxf(m0, fmaxf(m1, m2));
    float w0 = __expf(m0 - M), w1 = __expf(m1 - M), w2 = __expf(m2 - M);
    float denom = g_sm[b0*TI + ra]*w0 + g_sm[b1*TI + ra]*w1 + g_sm[b2*TI + ra]*w2;
    float inv = 1.f / denom;

    const float* a0 = &g_acc[(b0*VW + dg*10)*TI + ra];
    const float* a1 = &g_acc[(b1*VW + dg*10)*TI + ra];
    const float* a2 = &g_acc[(b2*VW + dg*10)*TI + ra];
    float* st = &stage[ra*STG + dg*10];
    #pragma unroll
    for (int u = 0; u < 10; u++)
        st[u] = (a0[u*TI]*w0 + a1[u*TI]*w1 + a2[u*TI]*w2) * inv;
    __syncthreads();

    // h output with residual
    {
        int r = tid >> 3, c0 = (tid & 7) * 8;
        int gi = ((it*TI + r)*LDIM + l)*HDIM + c0;
        const float* sg = &stage[r*STG + c0];
        float4 h0 = *(const float4*)&hin[gi];
        float4 h1 = *(const float4*)&hin[gi + 4];
        *(float4*)&out[gi] =
            make_float4(h0.x + sg[0], h0.y + sg[1], h0.z + sg[2], h0.w + sg[3]);
        *(float4*)&out[gi + 4] =
            make_float4(h1.x + sg[4], h1.y + sg[5], h1.z + sg[6], h1.w + sg[7]);
    }
    // coord output: out = coord*(1+S1[k]) - S2[k][t]
    for (int e = tid; e < TI*12; e += 256) {
        int r = e / 12, idx = e % 12, k = idx / 3;
        float S1 = stage[r*STG + 64 + k];
        float S2 = stage[r*STG + 68 + idx];
        int off = ((it*TI + r)*LDIM + l)*12 + idx;
        out[COUT_OFF + off] = coord[off] * (1.f + S1) - S2;
    }
}

// ==================== launch ====================
extern "C" void kernel_launch(void* const* d_in, const int* in_sizes, int n_in,
                              void* d_out, int out_size) {
    const float* h     = (const float*)d_in[0];
    const float* coord = (const float*)d_in[1];
    const float* wq1 = (const float*)d_in[2];
    const float* bq1 = (const float*)d_in[3];
    const float* wq2 = (const float*)d_in[4];
    const float* bq2 = (const float*)d_in[5];
    const float* wk1 = (const float*)d_in[6];
    const float* bk1 = (const float*)d_in[7];
    const float* wk2 = (const float*)d_in[8];
    const float* bk2 = (const float*)d_in[9];
    const float* wv1 = (const float*)d_in[10];
    const float* bv1 = (const float*)d_in[11];
    const float* wv2 = (const float*)d_in[12];
    const float* bv2 = (const float*)d_in[13];
    const float* wc1 = (const float*)d_in[14];
    const float* bc1 = (const float*)d_in[15];
    const float* wc2 = (const float*)d_in[16];
    float* out = (float*)d_out;

    cudaFuncSetAttribute(mlp_kernel, cudaFuncAttributeMaxDynamicSharedMemorySize, M_BYTES);
    mlp_kernel<<<dim3(NROWS/MROWS, 3), MTHR, M_BYTES>>>(h, coord, wq1, bq1, wq2, bq2,
                                                        wk1, bk1, wk2, bk2, wv1, bv1, wv2, bv2,
                                                        wc1, bc1, wc2);

    cudaFuncSetAttribute(attn_part_kernel, cudaFuncAttributeMaxDynamicSharedMemorySize, B1_BYTES);
    attn_part_kernel<<<dim3(NIT, LDIM, JSPLIT), 256, B1_BYTES>>>();

    combine_kernel<<<dim3(NIT, LDIM), 256>>>(h, coord, out);
}

// round 12
// speedup vs baseline: 2.9891x; 1.0481x over previous
#include <cuda_runtime.h>
#include <cstdint>

#define NTOK 768
#define LDIM 8
#define HDIM 64
#define NROWS (NTOK*LDIM)          // 6144
#define HOUT_ELEMS (NROWS*HDIM)    // 393216
#define COUT_OFF HOUT_ELEMS

#define TI 32
#define TJ 64
#define JSPLIT 3
#define TPS 4                      // tiles per split (12 total / 3)
#define NIT (NTOK/TI)              // 24
#define SLOTS (NIT*LDIM*JSPLIT)    // 576
#define VW 80

// -------- scratch (no allocations allowed) --------
__device__ float g_q[NROWS*HDIM];
__device__ float g_k[NROWS*HDIM];
__device__ float g_v[NROWS*HDIM];
__device__ float g_cmv[NROWS*4];
__device__ float g_cmvc[NROWS*12];
__device__ float g_acc[SLOTS*VW*TI];   // [slot][d][row] for coalescing
__device__ float g_mx[SLOTS*TI];
__device__ float g_sm[SLOTS*TI];

using u64 = unsigned long long;

__device__ __forceinline__ u64 ffma2(u64 a, u64 b, u64 c) {
    u64 d; asm("fma.rn.f32x2 %0, %1, %2, %3;" : "=l"(d) : "l"(a), "l"(b), "l"(c)); return d;
}
__device__ __forceinline__ u64 mul2(u64 a, u64 b) {
    u64 d; asm("mul.rn.f32x2 %0, %1, %2;" : "=l"(d) : "l"(a), "l"(b)); return d;
}
__device__ __forceinline__ u64 pack2(float x, float y) {
    u64 r; asm("mov.b64 %0, {%1, %2};" : "=l"(r) : "f"(x), "f"(y)); return r;
}
__device__ __forceinline__ float2 unpk(u64 v) {
    float2 f; asm("mov.b64 {%0, %1}, %2;" : "=f"(f.x), "=f"(f.y) : "l"(v)); return f;
}

__device__ __forceinline__ void cp16(uint32_t s, const void* g) {
    asm volatile("cp.async.cg.shared.global [%0], [%1], 16;" :: "r"(s), "l"(g));
}
#define CP_COMMIT() asm volatile("cp.async.commit_group;" ::: "memory")
#define CP_WAIT(n)  asm volatile("cp.async.wait_group %0;" :: "n"(n) : "memory")

// ==================== Kernel A: MLPs v4 (R6 shape + cp.async weight pipeline) ====================
#define MROWS 128
#define AST 72     // activation row stride: 64 cols + 4-pad after col 32 + 4 tail
#define WST 68     // weight row stride: 64 outs + 4-pad after out 32

// mlp smem layout (floats)
#define M_BUFA 0
#define M_BUFB (MROWS*AST)            // 9216
#define M_WA   (2*MROWS*AST)          // 18432
#define M_WB   (M_WA + 64*WST)        // 22784
#define M_FLOATS (M_WB + 64*WST)      // 27136
#define M_BYTES (M_FLOATS*4)          // 108544

// async load of a 64x64 weight matrix into padded layout: W[c][o] at c*WST + o + (o>=32?4:0)
__device__ __forceinline__ void cp_wpad(const float* __restrict__ wg, uint32_t sW_s, int tid) {
    #pragma unroll
    for (int i = 0; i < 4; i++) {
        int idx = tid + i*256;               // float4 index 0..1023
        int c = idx >> 4;
        int o = (idx & 15) * 4;
        uint32_t off = (uint32_t)(c*WST + o + (o >= 32 ? 4 : 0)) * 4u;
        cp16(sW_s + off, ((const float4*)wg) + idx);
    }
}

// one 64->64 layer + ReLU for 4 rows per thread (rows r, r+32, r+64, r+96).
__device__ __forceinline__ void layerv2(const float* __restrict__ in, const float* __restrict__ sW,
                                        const float* __restrict__ bg,
                                        float* outs, float* outg,
                                        int r, int o0, int wof, int row0) {
    float4 b0 = *(const float4*)&bg[o0];
    float4 b1 = *(const float4*)&bg[o0 + 4];
    u64 acc[4][4];
    #pragma unroll
    for (int k = 0; k < 4; k++) {
        acc[k][0] = pack2(b0.x, b0.y); acc[k][1] = pack2(b0.z, b0.w);
        acc[k][2] = pack2(b1.x, b1.y); acc[k][3] = pack2(b1.z, b1.w);
    }
    const float* in0 = in + r*AST;
    #pragma unroll
    for (int half = 0; half < 2; half++) {
        int coff = half * 36;                    // activation padded offset
        const float* wrow = sW + half*32*WST + wof;
        const float* ip = in0 + coff;
        #pragma unroll 8
        for (int c2 = 0; c2 < 32; c2++) {
            float h0 = ip[c2];
            float h1 = ip[32*AST + c2];
            float h2 = ip[64*AST + c2];
            float h3 = ip[96*AST + c2];
            ulonglong2 wa = *(const ulonglong2*)(wrow + c2*WST);
            ulonglong2 wb = *(const ulonglong2*)(wrow + c2*WST + 4);
            u64 hh;
            hh = pack2(h0, h0);
            acc[0][0] = ffma2(hh, wa.x, acc[0][0]); acc[0][1] = ffma2(hh, wa.y, acc[0][1]);
            acc[0][2] = ffma2(hh, wb.x, acc[0][2]); acc[0][3] = ffma2(hh, wb.y, acc[0][3]);
            hh = pack2(h1, h1);
            acc[1][0] = ffma2(hh, wa.x, acc[1][0]); acc[1][1] = ffma2(hh, wa.y, acc[1][1]);
            acc[1][2] = ffma2(hh, wb.x, acc[1][2]); acc[1][3] = ffma2(hh, wb.y, acc[1][3]);
            hh = pack2(h2, h2);
            acc[2][0] = ffma2(hh, wa.x, acc[2][0]); acc[2][1] = ffma2(hh, wa.y, acc[2][1]);
            acc[2][2] = ffma2(hh, wb.x, acc[2][2]); acc[2][3] = ffma2(hh, wb.y, acc[2][3]);
            hh = pack2(h3, h3);
            acc[3][0] = ffma2(hh, wa.x, acc[3][0]); acc[3][1] = ffma2(hh, wa.y, acc[3][1]);
            acc[3][2] = ffma2(hh, wb.x, acc[3][2]); acc[3][3] = ffma2(hh, wb.y, acc[3][3]);
        }
    }
    #pragma unroll
    for (int k = 0; k < 4; k++) {
        float2 f0 = unpk(acc[k][0]), f1 = unpk(acc[k][1]);
        float2 f2 = unpk(acc[k][2]), f3 = unpk(acc[k][3]);
        float4 lo = make_float4(fmaxf(f0.x,0.f), fmaxf(f0.y,0.f), fmaxf(f1.x,0.f), fmaxf(f1.y,0.f));
        float4 hi = make_float4(fmaxf(f2.x,0.f), fmaxf(f2.y,0.f), fmaxf(f3.x,0.f), fmaxf(f3.y,0.f));
        int rr = r + 32*k;
        if (outs) {
            float* d = &outs[rr*AST + wof];
            *(float4*)d = lo; *(float4*)(d + 4) = hi;
        }
        if (outg) {
            float* d = &outg[(row0 + rr)*HDIM + o0];
            *(float4*)d = lo; *(float4*)(d + 4) = hi;
        }
    }
}

__global__ __launch_bounds__(256) void mlp_kernel(
    const float* __restrict__ h, const float* __restrict__ coord,
    const float* __restrict__ wq1, const float* __restrict__ bq1,
    const float* __restrict__ wq2, const float* __restrict__ bq2,
    const float* __restrict__ wk1, const float* __restrict__ bk1,
    const float* __restrict__ wk2, const float* __restrict__ bk2,
    const float* __restrict__ wv1, const float* __restrict__ bv1,
    const float* __restrict__ wv2, const float* __restrict__ bv2,
    const float* __restrict__ wc1, const float* __restrict__ bc1,
    const float* __restrict__ wc2)
{
    extern __shared__ float sm[];
    float* bufA = sm + M_BUFA;
    float* bufB = sm + M_BUFB;
    float* sWa  = sm + M_WA;
    float* sWb  = sm + M_WB;

    int tid = threadIdx.x;
    int row0 = blockIdx.x * MROWS;
    int chain = blockIdx.y;
    int r = tid >> 3;                 // 0..31
    int o0 = (tid & 7) * 8;
    int wof = o0 + (o0 >= 32 ? 4 : 0);

    uint32_t bufA_s = (uint32_t)__cvta_generic_to_shared(bufA);
    uint32_t sWa_s  = (uint32_t)__cvta_generic_to_shared(sWa);
    uint32_t sWb_s  = (uint32_t)__cvta_generic_to_shared(sWb);

    const float *w1, *b1, *w2, *b2;
    float* gout;
    if (chain == 0)      { w1 = wq1; b1 = bq1; w2 = wq2; b2 = bq2; gout = g_q; }
    else if (chain == 1) { w1 = wk1; b1 = bk1; w2 = wk2; b2 = bk2; gout = g_k; }
    else                 { w1 = wv1; b1 = bv1; w2 = wv2; b2 = bv2; gout = g_v; }

    // prologue: async W1 + h tile
    cp_wpad(w1, sWa_s, tid);
    #pragma unroll
    for (int k = 0; k < 4; k++) {
        int rr = r + 32*k;
        const float* src = &h[(row0 + rr)*HDIM + o0];
        uint32_t dst = bufA_s + (uint32_t)(rr*AST + wof)*4u;
        cp16(dst, src);
        cp16(dst + 16, src + 4);
    }
    CP_COMMIT();
    CP_WAIT(0);
    __syncthreads();

    // prefetch W2 during layer 1
    cp_wpad(w2, sWb_s, tid); CP_COMMIT();
    layerv2(bufA, sWa, b1, bufB, (float*)0, r, o0, wof, row0);
    CP_WAIT(0);
    __syncthreads();

    if (chain != 2) {
        layerv2(bufB, sWb, b2, (float*)0, gout, r, o0, wof, row0);
        return;
    }

    // chain 2: prefetch wc1 into sWa during layer 2
    cp_wpad(wc1, sWa_s, tid); CP_COMMIT();
    layerv2(bufB, sWb, b2, bufA, gout, r, o0, wof, row0);
    CP_WAIT(0);
    __syncthreads();

    // prefetch wc2 into sWb (compact 64x4 layout) during layer 3
    if (tid < 64) cp16(sWb_s + tid*16u, ((const float4*)wc2) + tid);
    CP_COMMIT();
    layerv2(bufA, sWa, bc1, bufB, (float*)0, r, o0, wof, row0);
    CP_WAIT(0);
    __syncthreads();

    // final: cmv = hidden @ wc2 (64 -> 4), 2 outputs per thread
    if (tid < 256) {
        int rr = tid >> 1;            // 0..127
        int ob = (tid & 1) * 2;
        float a0 = 0.f, a1 = 0.f;
        const float* inr = &bufB[rr*AST];
        const float* sW = sWb;
        #pragma unroll 8
        for (int c = 0; c < 32; c++) {
            float x = inr[c];
            a0 += x * sW[c*4 + ob];
            a1 += x * sW[c*4 + ob + 1];
        }
        #pragma unroll 8
        for (int c = 32; c < 64; c++) {
            float x = inr[c + 4];
            a0 += x * sW[c*4 + ob];
            a1 += x * sW[c*4 + ob + 1];
        }
        int row = row0 + rr;
        g_cmv[row*4 + ob]     = a0;
        g_cmv[row*4 + ob + 1] = a1;
        #pragma unroll
        for (int t = 0; t < 3; t++) {
            g_cmvc[row*12 + ob*3 + t]     = a0 * coord[row*12 + ob*3 + t];
            g_cmvc[row*12 + (ob+1)*3 + t] = a1 * coord[row*12 + (ob+1)*3 + t];
        }
    }
}

// ==================== Kernel B1: flash attention partials (cp.async pipelined) ====================
#define KSTR 68   // multiple of 4: 16B alignment for float4/cp.async
#define SSTR 33

#define OQT 0
#define OK  2048                    // 64 cols x 32 rows
#define OV  (OK + TJ*KSTR)          // 6400
#define OS  (OV + TJ*VW)            // 11520
#define OC  (OS + TJ*SSTR)          // 13632
#define B1_FLOATS (OC + TI)         // 13664
#define B1_BYTES (B1_FLOATS*4)      // 54656

__device__ __forceinline__ void issue_k_tile(uint32_t kp_s, int jb, int l, int tid) {
    int j = tid >> 2, c0 = (tid & 3) * 16;
    const float* src = &g_k[((jb + j)*LDIM + l)*HDIM + c0];
    uint32_t d = kp_s + (uint32_t)(j*KSTR + c0)*4u;
    #pragma unroll
    for (int q4 = 0; q4 < 4; q4++) cp16(d + q4*16, src + q4*4);
}
__device__ __forceinline__ void issue_v_tile(uint32_t vt_s, int jb, int l, int tid) {
    int j = tid >> 2, c0 = (tid & 3) * 16;
    const float* src = &g_v[((jb + j)*LDIM + l)*HDIM + c0];
    uint32_t d = vt_s + (uint32_t)(j*VW + c0)*4u;
    #pragma unroll
    for (int q4 = 0; q4 < 4; q4++) cp16(d + q4*16, src + q4*4);
    if (tid < TJ) {
        int grow = (jb + tid)*LDIM + l;
        uint32_t dv = vt_s + (uint32_t)(tid*VW + 64)*4u;
        cp16(dv, &g_cmv[grow*4]);
        const float* cc = &g_cmvc[grow*12];
        cp16(dv + 16, cc);
        cp16(dv + 32, cc + 4);
        cp16(dv + 48, cc + 8);
    }
}

__global__ __launch_bounds__(256, 4) void attn_part_kernel()
{
    extern __shared__ float smf[];
    float* qT = smf + OQT;
    float* kp = smf + OK;
    float* vt = smf + OV;
    float* S  = smf + OS;
    float* cb = smf + OC;

    int tid = threadIdx.x;
    int it = blockIdx.x, l = blockIdx.y, sp = blockIdx.z;
    int i0 = it * TI;
    int j0 = sp * (TPS*TJ);

    uint32_t kp_s = (uint32_t)__cvta_generic_to_shared(kp);
    uint32_t vt_s = (uint32_t)__cvta_generic_to_shared(vt);

    // prologue: start async loads of tile 0
    issue_k_tile(kp_s, j0, l, tid); CP_COMMIT();
    issue_v_tile(vt_s, j0, l, tid); CP_COMMIT();

    // load q tile transposed: qT[c][r] (overlaps with async loads)
    {
        int r = tid >> 3, c0 = (tid & 7) * 8;
        const float* src = &g_q[((i0 + r)*LDIM + l)*HDIM + c0];
        float4 a = *(const float4*)src;
        float4 b = *(const float4*)(src + 4);
        float v8[8] = {a.x, a.y, a.z, a.w, b.x, b.y, b.z, b.w};
        #pragma unroll
        for (int u = 0; u < 8; u++) qT[(c0 + u)*TI + r] = v8[u];
    }

    int rg = tid & 7, jg = tid >> 3, r0 = rg * 4, jj = jg * 2;  // phase1 roles
    int row = tid >> 3, sub = tid & 7;                          // phase2 roles
    int ra = tid & 31, dg = tid >> 5;                           // phase3 roles
    int cbase = (dg < 4) ? dg*12 : 48 + (dg - 4)*8;             // 16B-aligned chunks

    float m_reg = -1e30f, s_reg = 0.f;
    u64 ac[6] = {0, 0, 0, 0, 0, 0};

    #pragma unroll
    for (int t = 0; t < TPS; t++) {
        int jb = j0 + t*TJ;

        CP_WAIT(1);            // K(t) complete (V(t) may still be in flight)
        __syncthreads();

        // ---- phase 1: scores -> S[j][r] (transposed) ----
        {
            u64 a00 = 0, a01 = 0, a10 = 0, a11 = 0;
            const float* kr0 = &kp[jj*KSTR];
            const float* kr1 = &kp[(jj + 1)*KSTR];
            #pragma unroll 8
            for (int c = 0; c < 64; c++) {
                u64 q01 = *(const u64*)&qT[c*TI + r0];
                u64 q23 = *(const u64*)&qT[c*TI + r0 + 2];
                float k0v = kr0[c], k1v = kr1[c];
                u64 k0 = pack2(k0v, k0v);
                u64 k1 = pack2(k1v, k1v);
                a00 = ffma2(q01, k0, a00);
                a01 = ffma2(q23, k0, a01);
                a10 = ffma2(q01, k1, a10);
                a11 = ffma2(q23, k1, a11);
            }
            float2 f;
            f = unpk(a00); S[jj*SSTR + r0]     = f.x; S[jj*SSTR + r0 + 1]     = f.y;
            f = unpk(a01); S[jj*SSTR + r0 + 2] = f.x; S[jj*SSTR + r0 + 3]     = f.y;
            f = unpk(a10); S[(jj+1)*SSTR + r0]     = f.x; S[(jj+1)*SSTR + r0 + 1] = f.y;
            f = unpk(a11); S[(jj+1)*SSTR + r0 + 2] = f.x; S[(jj+1)*SSTR + r0 + 3] = f.y;
        }
        __syncthreads();

        // K buffer free: prefetch K(t+1)
        if (t < TPS-1) { issue_k_tile(kp_s, jb + TJ, l, tid); CP_COMMIT(); }

        // ---- phase 2: online softmax update ----
        {
            float tm = -1e30f;
            #pragma unroll
            for (int j = sub; j < TJ; j += 8) tm = fmaxf(tm, S[j*SSTR + row]);
            #pragma unroll
            for (int w = 4; w >= 1; w >>= 1) tm = fmaxf(tm, __shfl_xor_sync(0xffffffffu, tm, w));
            float newm = fmaxf(m_reg, tm);
            float cc = __expf(m_reg - newm);
            float ts = 0.f;
            #pragma unroll
            for (int j = sub; j < TJ; j += 8) {
                float e = __expf(S[j*SSTR + row] - newm);
                S[j*SSTR + row] = e;
                ts += e;
            }
            #pragma unroll
            for (int w = 4; w >= 1; w >>= 1) ts += __shfl_xor_sync(0xffffffffu, ts, w);
            s_reg = s_reg*cc + ts;
            m_reg = newm;
            if (sub == 0) cb[row] = cc;
        }
        if (t < TPS-1) { CP_WAIT(1); } else { CP_WAIT(0); }   // V(t) complete
        __syncthreads();

        // ---- phase 3: rescale + accumulate p @ [V|cmv|cmvc] ----
        {
            float cc = cb[ra];
            u64 c2 = pack2(cc, cc);
            const float* vb = vt + cbase;
            if (dg < 4) {
                #pragma unroll
                for (int u = 0; u < 6; u++) ac[u] = mul2(ac[u], c2);
                #pragma unroll 4
                for (int j = 0; j < TJ; j++) {
                    float p = S[j*SSTR + ra];
                    u64 p2 = pack2(p, p);
                    const float* vr = vb + j*VW;
                    ulonglong2 v01 = *(const ulonglong2*)(vr);
                    ulonglong2 v23 = *(const ulonglong2*)(vr + 4);
                    ulonglong2 v45 = *(const ulonglong2*)(vr + 8);
                    ac[0] = ffma2(p2, v01.x, ac[0]);
                    ac[1] = ffma2(p2, v01.y, ac[1]);
                    ac[2] = ffma2(p2, v23.x, ac[2]);
                    ac[3] = ffma2(p2, v23.y, ac[3]);
                    ac[4] = ffma2(p2, v45.x, ac[4]);
                    ac[5] = ffma2(p2, v45.y, ac[5]);
                }
            } else {
                #pragma unroll
                for (int u = 0; u < 4; u++) ac[u] = mul2(ac[u], c2);
                #pragma unroll 4
                for (int j = 0; j < TJ; j++) {
                    float p = S[j*SSTR + ra];
                    u64 p2 = pack2(p, p);
                    const float* vr = vb + j*VW;
                    ulonglong2 v01 = *(const ulonglong2*)(vr);
                    ulonglong2 v23 = *(const ulonglong2*)(vr + 4);
                    ac[0] = ffma2(p2, v01.x, ac[0]);
                    ac[1] = ffma2(p2, v01.y, ac[1]);
                    ac[2] = ffma2(p2, v23.x, ac[2]);
                    ac[3] = ffma2(p2, v23.y, ac[3]);
                }
            }
        }
        __syncthreads();

        // V buffer free: prefetch V(t+1)
        if (t < TPS-1) { issue_v_tile(vt_s, jb + TJ, l, tid); CP_COMMIT(); }
    }

    // write partials
    int slot = (sp*LDIM + l)*NIT + it;
    if (sub == 0) {
        g_mx[slot*TI + row] = m_reg;
        g_sm[slot*TI + row] = s_reg;
    }
    // g_acc layout [slot][d][row]: coalesced stores (lanes = consecutive ra)
    {
        float* ga = &g_acc[(slot*VW + cbase)*TI + ra];
        if (dg < 4) {
            #pragma unroll
            for (int u = 0; u < 6; u++) {
                float2 f = unpk(ac[u]);
                ga[(u*2    )*TI] = f.x;
                ga[(u*2 + 1)*TI] = f.y;
            }
        } else {
            #pragma unroll
            for (int u = 0; u < 4; u++) {
                float2 f = unpk(ac[u]);
                ga[(u*2    )*TI] = f.x;
                ga[(u*2 + 1)*TI] = f.y;
            }
        }
    }
}

// ==================== Kernel B2: combine + epilogue ====================
#define STG 81   // padded stage stride (conflict-free)

__global__ __launch_bounds__(256) void combine_kernel(
    const float* __restrict__ hin, const float* __restrict__ coord,
    float* __restrict__ out)
{
    __shared__ float stage[TI*STG];
    int tid = threadIdx.x;
    int it = blockIdx.x, l = blockIdx.y;
    int ra = tid & 31, dg = tid >> 5;

    int b0 = ((0*LDIM + l)*NIT + it);
    int b1 = ((1*LDIM + l)*NIT + it);
    int b2 = ((2*LDIM + l)*NIT + it);

    float m0 = g_mx[b0*TI + ra], m1 = g_mx[b1*TI + ra], m2 = g_mx[b2*TI + ra];
    float M = fmaxf(m0, fmaxf(m1, m2));
    float w0 = __expf(m0 - M), w1 = __expf(m1 - M), w2 = __expf(m2 - M);
    float denom = g_sm[b0*TI + ra]*w0 + g_sm[b1*TI + ra]*w1 + g_sm[b2*TI + ra]*w2;
    float inv = 1.f / denom;

    const float* a0 = &g_acc[(b0*VW + dg*10)*TI + ra];
    const float* a1 = &g_acc[(b1*VW + dg*10)*TI + ra];
    const float* a2 = &g_acc[(b2*VW + dg*10)*TI + ra];
    float* st = &stage[ra*STG + dg*10];
    #pragma unroll
    for (int u = 0; u < 10; u++)
        st[u] = (a0[u*TI]*w0 + a1[u*TI]*w1 + a2[u*TI]*w2) * inv;
    __syncthreads();

    // h output with residual
    {
        int r = tid >> 3, c0 = (tid & 7) * 8;
        int gi = ((it*TI + r)*LDIM + l)*HDIM + c0;
        const float* sg = &stage[r*STG + c0];
        float4 h0 = *(const float4*)&hin[gi];
        float4 h1 = *(const float4*)&hin[gi + 4];
        *(float4*)&out[gi] =
            make_float4(h0.x + sg[0], h0.y + sg[1], h0.z + sg[2], h0.w + sg[3]);
        *(float4*)&out[gi + 4] =
            make_float4(h1.x + sg[4], h1.y + sg[5], h1.z + sg[6], h1.w + sg[7]);
    }
    // coord output: out = coord*(1+S1[k]) - S2[k][t]
    for (int e = tid; e < TI*12; e += 256) {
        int r = e / 12, idx = e % 12, k = idx / 3;
        float S1 = stage[r*STG + 64 + k];
        float S2 = stage[r*STG + 68 + idx];
        int off = ((it*TI + r)*LDIM + l)*12 + idx;
        out[COUT_OFF + off] = coord[off] * (1.f + S1) - S2;
    }
}

// ==================== launch ====================
extern "C" void kernel_launch(void* const* d_in, const int* in_sizes, int n_in,
                              void* d_out, int out_size) {
    const float* h     = (const float*)d_in[0];
    const float* coord = (const float*)d_in[1];
    const float* wq1 = (const float*)d_in[2];
    const float* bq1 = (const float*)d_in[3];
    const float* wq2 = (const float*)d_in[4];
    const float* bq2 = (const float*)d_in[5];
    const float* wk1 = (const float*)d_in[6];
    const float* bk1 = (const float*)d_in[7];
    const float* wk2 = (const float*)d_in[8];
    const float* bk2 = (const float*)d_in[9];
    const float* wv1 = (const float*)d_in[10];
    const float* bv1 = (const float*)d_in[11];
    const float* wv2 = (const float*)d_in[12];
    const float* bv2 = (const float*)d_in[13];
    const float* wc1 = (const float*)d_in[14];
    const float* bc1 = (const float*)d_in[15];
    const float* wc2 = (const float*)d_in[16];
    float* out = (float*)d_out;

    cudaFuncSetAttribute(mlp_kernel, cudaFuncAttributeMaxDynamicSharedMemorySize, M_BYTES);
    mlp_kernel<<<dim3(NROWS/MROWS, 3), 256, M_BYTES>>>(h, coord, wq1, bq1, wq2, bq2,
                                                       wk1, bk1, wk2, bk2, wv1, bv1, wv2, bv2,
                                                       wc1, bc1, wc2);

    cudaFuncSetAttribute(attn_part_kernel, cudaFuncAttributeMaxDynamicSharedMemorySize, B1_BYTES);
    attn_part_kernel<<<dim3(NIT, LDIM, JSPLIT), 256, B1_BYTES>>>();

    combine_kernel<<<dim3(NIT, LDIM), 256>>>(h, coord, out);
}

// round 13
// speedup vs baseline: 3.0101x; 1.0070x over previous
#include <cuda_runtime.h>
#include <cstdint>

#define NTOK 768
#define LDIM 8
#define HDIM 64
#define NROWS (NTOK*LDIM)          // 6144
#define HOUT_ELEMS (NROWS*HDIM)    // 393216
#define COUT_OFF HOUT_ELEMS

#define TI 32
#define TJ 64
#define JSPLIT 3
#define TPS 4                      // tiles per split (12 total / 3)
#define NIT (NTOK/TI)              // 24
#define SLOTS (NIT*LDIM*JSPLIT)    // 576
#define VW 80

// -------- scratch (no allocations allowed) --------
__device__ float g_q[NROWS*HDIM];
__device__ float g_k[NROWS*HDIM];
__device__ float g_v[NROWS*HDIM];
__device__ float g_cmv[NROWS*4];
__device__ float g_cmvc[NROWS*12];
__device__ float g_acc[SLOTS*VW*TI];   // [slot][d][row] for coalescing
__device__ float g_mx[SLOTS*TI];
__device__ float g_sm[SLOTS*TI];
__device__ unsigned int g_cnt[NIT*LDIM];   // last-block tickets (self-resetting)

using u64 = unsigned long long;

__device__ __forceinline__ u64 ffma2(u64 a, u64 b, u64 c) {
    u64 d; asm("fma.rn.f32x2 %0, %1, %2, %3;" : "=l"(d) : "l"(a), "l"(b), "l"(c)); return d;
}
__device__ __forceinline__ u64 mul2(u64 a, u64 b) {
    u64 d; asm("mul.rn.f32x2 %0, %1, %2;" : "=l"(d) : "l"(a), "l"(b)); return d;
}
__device__ __forceinline__ u64 pack2(float x, float y) {
    u64 r; asm("mov.b64 %0, {%1, %2};" : "=l"(r) : "f"(x), "f"(y)); return r;
}
__device__ __forceinline__ float2 unpk(u64 v) {
    float2 f; asm("mov.b64 {%0, %1}, %2;" : "=f"(f.x), "=f"(f.y) : "l"(v)); return f;
}

__device__ __forceinline__ void cp16(uint32_t s, const void* g) {
    asm volatile("cp.async.cg.shared.global [%0], [%1], 16;" :: "r"(s), "l"(g));
}
#define CP_COMMIT() asm volatile("cp.async.commit_group;" ::: "memory")
#define CP_WAIT(n)  asm volatile("cp.async.wait_group %0;" :: "n"(n) : "memory")

// ==================== Kernel A: MLPs v5 (128 thr / 64-row tiles, 3 CTA/SM) ====================
#define MROWS 64
#define MTHR 128
#define AST 72     // activation row stride: 64 cols + 4-pad after col 32 + 4 tail
#define WST 68     // weight row stride: 64 outs + 4-pad after out 32

// mlp smem layout (floats)
#define M_BUFA 0
#define M_BUFB (MROWS*AST)            // 4608
#define M_WA   (2*MROWS*AST)          // 9216
#define M_WB   (M_WA + 64*WST)        // 13568
#define M_FLOATS (M_WB + 64*WST)      // 17920
#define M_BYTES (M_FLOATS*4)          // 71680

// async load of a 64x64 weight matrix into padded layout: W[c][o] at c*WST + o + (o>=32?4:0)
__device__ __forceinline__ void cp_wpad(const float* __restrict__ wg, uint32_t sW_s, int tid) {
    #pragma unroll
    for (int i = 0; i < 8; i++) {
        int idx = tid + i*MTHR;              // float4 index 0..1023
        int c = idx >> 4;
        int o = (idx & 15) * 4;
        uint32_t off = (uint32_t)(c*WST + o + (o >= 32 ? 4 : 0)) * 4u;
        cp16(sW_s + off, ((const float4*)wg) + idx);
    }
}

// one 64->64 layer + ReLU for 4 rows per thread (rows r, r+16, r+32, r+48).
__device__ __forceinline__ void layerv2(const float* __restrict__ in, const float* __restrict__ sW,
                                        const float* __restrict__ bg,
                                        float* outs, float* outg,
                                        int r, int o0, int wof, int row0) {
    float4 b0 = *(const float4*)&bg[o0];
    float4 b1 = *(const float4*)&bg[o0 + 4];
    u64 acc[4][4];
    #pragma unroll
    for (int k = 0; k < 4; k++) {
        acc[k][0] = pack2(b0.x, b0.y); acc[k][1] = pack2(b0.z, b0.w);
        acc[k][2] = pack2(b1.x, b1.y); acc[k][3] = pack2(b1.z, b1.w);
    }
    const float* in0 = in + r*AST;
    #pragma unroll
    for (int half = 0; half < 2; half++) {
        int coff = half * 36;                    // activation padded offset
        const float* wrow = sW + half*32*WST + wof;
        const float* ip = in0 + coff;
        #pragma unroll 8
        for (int c2 = 0; c2 < 32; c2++) {
            float h0 = ip[c2];
            float h1 = ip[16*AST + c2];
            float h2 = ip[32*AST + c2];
            float h3 = ip[48*AST + c2];
            ulonglong2 wa = *(const ulonglong2*)(wrow + c2*WST);
            ulonglong2 wb = *(const ulonglong2*)(wrow + c2*WST + 4);
            u64 hh;
            hh = pack2(h0, h0);
            acc[0][0] = ffma2(hh, wa.x, acc[0][0]); acc[0][1] = ffma2(hh, wa.y, acc[0][1]);
            acc[0][2] = ffma2(hh, wb.x, acc[0][2]); acc[0][3] = ffma2(hh, wb.y, acc[0][3]);
            hh = pack2(h1, h1);
            acc[1][0] = ffma2(hh, wa.x, acc[1][0]); acc[1][1] = ffma2(hh, wa.y, acc[1][1]);
            acc[1][2] = ffma2(hh, wb.x, acc[1][2]); acc[1][3] = ffma2(hh, wb.y, acc[1][3]);
            hh = pack2(h2, h2);
            acc[2][0] = ffma2(hh, wa.x, acc[2][0]); acc[2][1] = ffma2(hh, wa.y, acc[2][1]);
            acc[2][2] = ffma2(hh, wb.x, acc[2][2]); acc[2][3] = ffma2(hh, wb.y, acc[2][3]);
            hh = pack2(h3, h3);
            acc[3][0] = ffma2(hh, wa.x, acc[3][0]); acc[3][1] = ffma2(hh, wa.y, acc[3][1]);
            acc[3][2] = ffma2(hh, wb.x, acc[3][2]); acc[3][3] = ffma2(hh, wb.y, acc[3][3]);
        }
    }
    #pragma unroll
    for (int k = 0; k < 4; k++) {
        float2 f0 = unpk(acc[k][0]), f1 = unpk(acc[k][1]);
        float2 f2 = unpk(acc[k][2]), f3 = unpk(acc[k][3]);
        float4 lo = make_float4(fmaxf(f0.x,0.f), fmaxf(f0.y,0.f), fmaxf(f1.x,0.f), fmaxf(f1.y,0.f));
        float4 hi = make_float4(fmaxf(f2.x,0.f), fmaxf(f2.y,0.f), fmaxf(f3.x,0.f), fmaxf(f3.y,0.f));
        int rr = r + 16*k;
        if (outs) {
            float* d = &outs[rr*AST + wof];
            *(float4*)d = lo; *(float4*)(d + 4) = hi;
        }
        if (outg) {
            float* d = &outg[(row0 + rr)*HDIM + o0];
            *(float4*)d = lo; *(float4*)(d + 4) = hi;
        }
    }
}

__global__ __launch_bounds__(MTHR) void mlp_kernel(
    const float* __restrict__ h, const float* __restrict__ coord,
    const float* __restrict__ wq1, const float* __restrict__ bq1,
    const float* __restrict__ wq2, const float* __restrict__ bq2,
    const float* __restrict__ wk1, const float* __restrict__ bk1,
    const float* __restrict__ wk2, const float* __restrict__ bk2,
    const float* __restrict__ wv1, const float* __restrict__ bv1,
    const float* __restrict__ wv2, const float* __restrict__ bv2,
    const float* __restrict__ wc1, const float* __restrict__ bc1,
    const float* __restrict__ wc2)
{
    extern __shared__ float sm[];
    float* bufA = sm + M_BUFA;
    float* bufB = sm + M_BUFB;
    float* sWa  = sm + M_WA;
    float* sWb  = sm + M_WB;

    int tid = threadIdx.x;
    int row0 = blockIdx.x * MROWS;
    int chain = blockIdx.y;
    int r = tid >> 3;                 // 0..15
    int o0 = (tid & 7) * 8;
    int wof = o0 + (o0 >= 32 ? 4 : 0);

    uint32_t bufA_s = (uint32_t)__cvta_generic_to_shared(bufA);
    uint32_t sWa_s  = (uint32_t)__cvta_generic_to_shared(sWa);
    uint32_t sWb_s  = (uint32_t)__cvta_generic_to_shared(sWb);

    const float *w1, *b1, *w2, *b2;
    float* gout;
    if (chain == 0)      { w1 = wq1; b1 = bq1; w2 = wq2; b2 = bq2; gout = g_q; }
    else if (chain == 1) { w1 = wk1; b1 = bk1; w2 = wk2; b2 = bk2; gout = g_k; }
    else                 { w1 = wv1; b1 = bv1; w2 = wv2; b2 = bv2; gout = g_v; }

    // prologue: async W1 + h tile
    cp_wpad(w1, sWa_s, tid);
    #pragma unroll
    for (int k = 0; k < 4; k++) {
        int rr = r + 16*k;
        const float* src = &h[(row0 + rr)*HDIM + o0];
        uint32_t dst = bufA_s + (uint32_t)(rr*AST + wof)*4u;
        cp16(dst, src);
        cp16(dst + 16, src + 4);
    }
    CP_COMMIT();
    CP_WAIT(0);
    __syncthreads();

    // prefetch W2 during layer 1
    cp_wpad(w2, sWb_s, tid); CP_COMMIT();
    layerv2(bufA, sWa, b1, bufB, (float*)0, r, o0, wof, row0);
    CP_WAIT(0);
    __syncthreads();

    if (chain != 2) {
        layerv2(bufB, sWb, b2, (float*)0, gout, r, o0, wof, row0);
        return;
    }

    // chain 2: prefetch wc1 into sWa during layer 2
    cp_wpad(wc1, sWa_s, tid); CP_COMMIT();
    layerv2(bufB, sWb, b2, bufA, gout, r, o0, wof, row0);
    CP_WAIT(0);
    __syncthreads();

    // prefetch wc2 into sWb (compact 64x4 layout) during layer 3
    if (tid < 64) cp16(sWb_s + tid*16u, ((const float4*)wc2) + tid);
    CP_COMMIT();
    layerv2(bufA, sWa, bc1, bufB, (float*)0, r, o0, wof, row0);
    CP_WAIT(0);
    __syncthreads();

    // final: cmv = hidden @ wc2 (64 -> 4), 2 outputs per thread (128 thr x 2 = 64 rows x 4 outs... 2 each)
    {
        int rr = tid >> 1;            // 0..63
        int ob = (tid & 1) * 2;
        float a0 = 0.f, a1 = 0.f;
        const float* inr = &bufB[rr*AST];
        const float* sW = sWb;
        #pragma unroll 8
        for (int c = 0; c < 32; c++) {
            float x = inr[c];
            a0 += x * sW[c*4 + ob];
            a1 += x * sW[c*4 + ob + 1];
        }
        #pragma unroll 8
        for (int c = 32; c < 64; c++) {
            float x = inr[c + 4];
            a0 += x * sW[c*4 + ob];
            a1 += x * sW[c*4 + ob + 1];
        }
        int row = row0 + rr;
        g_cmv[row*4 + ob]     = a0;
        g_cmv[row*4 + ob + 1] = a1;
        #pragma unroll
        for (int t = 0; t < 3; t++) {
            g_cmvc[row*12 + ob*3 + t]     = a0 * coord[row*12 + ob*3 + t];
            g_cmvc[row*12 + (ob+1)*3 + t] = a1 * coord[row*12 + (ob+1)*3 + t];
        }
    }
}

// ==================== Kernel B: flash attention partials + fused last-block combine ====================
#define KSTR 68   // multiple of 4: 16B alignment for float4/cp.async
#define SSTR 33
#define STG 81    // padded stage stride for combine (conflict-free)

#define OQT 0
#define OK  2048                    // 64 cols x 32 rows (also reused as combine stage: 32*81=2592 <= 64*68=4352)
#define OV  (OK + TJ*KSTR)          // 6400
#define OS  (OV + TJ*VW)            // 11520
#define OC  (OS + TJ*SSTR)          // 13632
#define OFLAG (OC + TI)             // 13664
#define B1_FLOATS (OFLAG + 1)       // 13665
#define B1_BYTES (B1_FLOATS*4)      // 54660

__device__ __forceinline__ void issue_k_tile(uint32_t kp_s, int jb, int l, int tid) {
    int j = tid >> 2, c0 = (tid & 3) * 16;
    const float* src = &g_k[((jb + j)*LDIM + l)*HDIM + c0];
    uint32_t d = kp_s + (uint32_t)(j*KSTR + c0)*4u;
    #pragma unroll
    for (int q4 = 0; q4 < 4; q4++) cp16(d + q4*16, src + q4*4);
}
__device__ __forceinline__ void issue_v_tile(uint32_t vt_s, int jb, int l, int tid) {
    int j = tid >> 2, c0 = (tid & 3) * 16;
    const float* src = &g_v[((jb + j)*LDIM + l)*HDIM + c0];
    uint32_t d = vt_s + (uint32_t)(j*VW + c0)*4u;
    #pragma unroll
    for (int q4 = 0; q4 < 4; q4++) cp16(d + q4*16, src + q4*4);
    if (tid < TJ) {
        int grow = (jb + tid)*LDIM + l;
        uint32_t dv = vt_s + (uint32_t)(tid*VW + 64)*4u;
        cp16(dv, &g_cmv[grow*4]);
        const float* cc = &g_cmvc[grow*12];
        cp16(dv + 16, cc);
        cp16(dv + 32, cc + 4);
        cp16(dv + 48, cc + 8);
    }
}

__global__ __launch_bounds__(256, 4) void attn_part_kernel(
    const float* __restrict__ hin, const float* __restrict__ coord,
    float* __restrict__ out)
{
    extern __shared__ float smf[];
    float* qT = smf + OQT;
    float* kp = smf + OK;
    float* vt = smf + OV;
    float* S  = smf + OS;
    float* cb = smf + OC;

    int tid = threadIdx.x;
    int it = blockIdx.x, l = blockIdx.y, sp = blockIdx.z;
    int i0 = it * TI;
    int j0 = sp * (TPS*TJ);

    uint32_t kp_s = (uint32_t)__cvta_generic_to_shared(kp);
    uint32_t vt_s = (uint32_t)__cvta_generic_to_shared(vt);

    // prologue: start async loads of tile 0
    issue_k_tile(kp_s, j0, l, tid); CP_COMMIT();
    issue_v_tile(vt_s, j0, l, tid); CP_COMMIT();

    // load q tile transposed: qT[c][r] (overlaps with async loads)
    {
        int r = tid >> 3, c0 = (tid & 7) * 8;
        const float* src = &g_q[((i0 + r)*LDIM + l)*HDIM + c0];
        float4 a = *(const float4*)src;
        float4 b = *(const float4*)(src + 4);
        float v8[8] = {a.x, a.y, a.z, a.w, b.x, b.y, b.z, b.w};
        #pragma unroll
        for (int u = 0; u < 8; u++) qT[(c0 + u)*TI + r] = v8[u];
    }

    int rg = tid & 7, jg = tid >> 3, r0 = rg * 4, jj = jg * 2;  // phase1 roles
    int row = tid >> 3, sub = tid & 7;                          // phase2 roles
    int ra = tid & 31, dg = tid >> 5;                           // phase3 roles
    int cbase = (dg < 4) ? dg*12 : 48 + (dg - 4)*8;             // 16B-aligned chunks

    float m_reg = -1e30f, s_reg = 0.f;
    u64 ac[6] = {0, 0, 0, 0, 0, 0};

    #pragma unroll
    for (int t = 0; t < TPS; t++) {
        int jb = j0 + t*TJ;

        CP_WAIT(1);            // K(t) complete (V(t) may still be in flight)
        __syncthreads();

        // ---- phase 1: scores -> S[j][r] (transposed) ----
        {
            u64 a00 = 0, a01 = 0, a10 = 0, a11 = 0;
            const float* kr0 = &kp[jj*KSTR];
            const float* kr1 = &kp[(jj + 1)*KSTR];
            #pragma unroll 8
            for (int c = 0; c < 64; c++) {
                u64 q01 = *(const u64*)&qT[c*TI + r0];
                u64 q23 = *(const u64*)&qT[c*TI + r0 + 2];
                float k0v = kr0[c], k1v = kr1[c];
                u64 k0 = pack2(k0v, k0v);
                u64 k1 = pack2(k1v, k1v);
                a00 = ffma2(q01, k0, a00);
                a01 = ffma2(q23, k0, a01);
                a10 = ffma2(q01, k1, a10);
                a11 = ffma2(q23, k1, a11);
            }
            float2 f;
            f = unpk(a00); S[jj*SSTR + r0]     = f.x; S[jj*SSTR + r0 + 1]     = f.y;
            f = unpk(a01); S[jj*SSTR + r0 + 2] = f.x; S[jj*SSTR + r0 + 3]     = f.y;
            f = unpk(a10); S[(jj+1)*SSTR + r0]     = f.x; S[(jj+1)*SSTR + r0 + 1] = f.y;
            f = unpk(a11); S[(jj+1)*SSTR + r0 + 2] = f.x; S[(jj+1)*SSTR + r0 + 3] = f.y;
        }
        __syncthreads();

        // K buffer free: prefetch K(t+1)
        if (t < TPS-1) { issue_k_tile(kp_s, jb + TJ, l, tid); CP_COMMIT(); }

        // ---- phase 2: online softmax update ----
        {
            float tm = -1e30f;
            #pragma unroll
            for (int j = sub; j < TJ; j += 8) tm = fmaxf(tm, S[j*SSTR + row]);
            #pragma unroll
            for (int w = 4; w >= 1; w >>= 1) tm = fmaxf(tm, __shfl_xor_sync(0xffffffffu, tm, w));
            float newm = fmaxf(m_reg, tm);
            float cc = __expf(m_reg - newm);
            float ts = 0.f;
            #pragma unroll
            for (int j = sub; j < TJ; j += 8) {
                float e = __expf(S[j*SSTR + row] - newm);
                S[j*SSTR + row] = e;
                ts += e;
            }
            #pragma unroll
            for (int w = 4; w >= 1; w >>= 1) ts += __shfl_xor_sync(0xffffffffu, ts, w);
            s_reg = s_reg*cc + ts;
            m_reg = newm;
            if (sub == 0) cb[row] = cc;
        }
        if (t < TPS-1) { CP_WAIT(1); } else { CP_WAIT(0); }   // V(t) complete
        __syncthreads();

        // ---- phase 3: rescale + accumulate p @ [V|cmv|cmvc] ----
        {
            float cc = cb[ra];
            u64 c2 = pack2(cc, cc);
            const float* vb = vt + cbase;
            if (dg < 4) {
                #pragma unroll
                for (int u = 0; u < 6; u++) ac[u] = mul2(ac[u], c2);
                #pragma unroll 4
                for (int j = 0; j < TJ; j++) {
                    float p = S[j*SSTR + ra];
                    u64 p2 = pack2(p, p);
                    const float* vr = vb + j*VW;
                    ulonglong2 v01 = *(const ulonglong2*)(vr);
                    ulonglong2 v23 = *(const ulonglong2*)(vr + 4);
                    ulonglong2 v45 = *(const ulonglong2*)(vr + 8);
                    ac[0] = ffma2(p2, v01.x, ac[0]);
                    ac[1] = ffma2(p2, v01.y, ac[1]);
                    ac[2] = ffma2(p2, v23.x, ac[2]);
                    ac[3] = ffma2(p2, v23.y, ac[3]);
                    ac[4] = ffma2(p2, v45.x, ac[4]);
                    ac[5] = ffma2(p2, v45.y, ac[5]);
                }
            } else {
                #pragma unroll
                for (int u = 0; u < 4; u++) ac[u] = mul2(ac[u], c2);
                #pragma unroll 4
                for (int j = 0; j < TJ; j++) {
                    float p = S[j*SSTR + ra];
                    u64 p2 = pack2(p, p);
                    const float* vr = vb + j*VW;
                    ulonglong2 v01 = *(const ulonglong2*)(vr);
                    ulonglong2 v23 = *(const ulonglong2*)(vr + 4);
                    ac[0] = ffma2(p2, v01.x, ac[0]);
                    ac[1] = ffma2(p2, v01.y, ac[1]);
                    ac[2] = ffma2(p2, v23.x, ac[2]);
                    ac[3] = ffma2(p2, v23.y, ac[3]);
                }
            }
        }
        __syncthreads();

        // V buffer free: prefetch V(t+1)
        if (t < TPS-1) { issue_v_tile(vt_s, jb + TJ, l, tid); CP_COMMIT(); }
    }

    // ---- write partials ----
    int slot = (sp*LDIM + l)*NIT + it;
    if (sub == 0) {
        g_mx[slot*TI + row] = m_reg;
        g_sm[slot*TI + row] = s_reg;
    }
    {
        float* ga = &g_acc[(slot*VW + cbase)*TI + ra];
        if (dg < 4) {
            #pragma unroll
            for (int u = 0; u < 6; u++) {
                float2 f = unpk(ac[u]);
                ga[(u*2    )*TI] = f.x;
                ga[(u*2 + 1)*TI] = f.y;
            }
        } else {
            #pragma unroll
            for (int u = 0; u < 4; u++) {
                float2 f = unpk(ac[u]);
                ga[(u*2    )*TI] = f.x;
                ga[(u*2 + 1)*TI] = f.y;
            }
        }
    }

    // ---- last-block ticket: the final split block for this (it,l) combines ----
    __threadfence();
    __syncthreads();
    if (tid == 0) {
        unsigned int o = atomicAdd(&g_cnt[l*NIT + it], 1u);
        bool last = (o == JSPLIT - 1);
        smf[OFLAG] = last ? 1.f : 0.f;
        if (last) g_cnt[l*NIT + it] = 0;     // reset for next launch/replay
    }
    __syncthreads();
    if (smf[OFLAG] == 0.f) return;

    // ---- fused combine (reuses kp region as stage) ----
    {
        float* stage = smf + OK;
        int b0 = ((0*LDIM + l)*NIT + it);
        int b1 = ((1*LDIM + l)*NIT + it);
        int b2 = ((2*LDIM + l)*NIT + it);

        float m0 = g_mx[b0*TI + ra], m1 = g_mx[b1*TI + ra], m2 = g_mx[b2*TI + ra];
        float M = fmaxf(m0, fmaxf(m1, m2));
        float w0 = __expf(m0 - M), w1 = __expf(m1 - M), w2 = __expf(m2 - M);
        float denom = g_sm[b0*TI + ra]*w0 + g_sm[b1*TI + ra]*w1 + g_sm[b2*TI + ra]*w2;
        float inv = 1.f / denom;

        const float* a0 = &g_acc[(b0*VW + dg*10)*TI + ra];
        const float* a1 = &g_acc[(b1*VW + dg*10)*TI + ra];
        const float* a2 = &g_acc[(b2*VW + dg*10)*TI + ra];
        float* st = &stage[ra*STG + dg*10];
        #pragma unroll
        for (int u = 0; u < 10; u++)
            st[u] = (a0[u*TI]*w0 + a1[u*TI]*w1 + a2[u*TI]*w2) * inv;
        __syncthreads();

        // h output with residual
        {
            int r = tid >> 3, c0 = (tid & 7) * 8;
            int gi = ((it*TI + r)*LDIM + l)*HDIM + c0;
            const float* sg = &stage[r*STG + c0];
            float4 h0 = *(const float4*)&hin[gi];
            float4 h1 = *(const float4*)&hin[gi + 4];
            *(float4*)&out[gi] =
                make_float4(h0.x + sg[0], h0.y + sg[1], h0.z + sg[2], h0.w + sg[3]);
            *(float4*)&out[gi + 4] =
                make_float4(h1.x + sg[4], h1.y + sg[5], h1.z + sg[6], h1.w + sg[7]);
        }
        // coord output: out = coord*(1+S1[k]) - S2[k][t]
        for (int e = tid; e < TI*12; e += 256) {
            int r = e / 12, idx = e % 12, k = idx / 3;
            float S1 = stage[r*STG + 64 + k];
            float S2 = stage[r*STG + 68 + idx];
            int off = ((it*TI + r)*LDIM + l)*12 + idx;
            out[COUT_OFF + off] = coord[off] * (1.f + S1) - S2;
        }
    }
}

// ==================== launch ====================
extern "C" void kernel_launch(void* const* d_in, const int* in_sizes, int n_in,
                              void* d_out, int out_size) {
    const float* h     = (const float*)d_in[0];
    const float* coord = (const float*)d_in[1];
    const float* wq1 = (const float*)d_in[2];
    const float* bq1 = (const float*)d_in[3];
    const float* wq2 = (const float*)d_in[4];
    const float* bq2 = (const float*)d_in[5];
    const float* wk1 = (const float*)d_in[6];
    const float* bk1 = (const float*)d_in[7];
    const float* wk2 = (const float*)d_in[8];
    const float* bk2 = (const float*)d_in[9];
    const float* wv1 = (const float*)d_in[10];
    const float* bv1 = (const float*)d_in[11];
    const float* wv2 = (const float*)d_in[12];
    const float* bv2 = (const float*)d_in[13];
    const float* wc1 = (const float*)d_in[14];
    const float* bc1 = (const float*)d_in[15];
    const float* wc2 = (const float*)d_in[16];
    float* out = (float*)d_out;

    cudaFuncSetAttribute(mlp_kernel, cudaFuncAttributeMaxDynamicSharedMemorySize, M_BYTES);
    mlp_kernel<<<dim3(NROWS/MROWS, 3), MTHR, M_BYTES>>>(h, coord, wq1, bq1, wq2, bq2,
                                                        wk1, bk1, wk2, bk2, wv1, bv1, wv2, bv2,
                                                        wc1, bc1, wc2);

    cudaFuncSetAttribute(attn_part_kernel, cudaFuncAttributeMaxDynamicSharedMemorySize, B1_BYTES);
    attn_part_kernel<<<dim3(NIT, LDIM, JSPLIT), 256, B1_BYTES>>>(h, coord, out);
}

// round 15
// speedup vs baseline: 3.0701x; 1.0199x over previous
#include <cuda_runtime.h>
#include <cstdint>

#define NTOK 768
#define LDIM 8
#define HDIM 64
#define NROWS (NTOK*LDIM)          // 6144
#define HOUT_ELEMS (NROWS*HDIM)    // 393216
#define COUT_OFF HOUT_ELEMS

#define TI 32
#define TJ 64
#define JSPLIT 3
#define TPS 4                      // tiles per split (12 total / 3)
#define NIT (NTOK/TI)              // 24
#define SLOTS (NIT*LDIM*JSPLIT)    // 576
#define VW 80

// -------- scratch (no allocations allowed) --------
__device__ float g_q[NROWS*HDIM];
__device__ float g_k[NROWS*HDIM];
__device__ float g_v[NROWS*HDIM];
__device__ float g_cmv[NROWS*4];
__device__ float g_cmvc[NROWS*12];
__device__ float g_acc[SLOTS*VW*TI];   // [slot][d][row] for coalescing
__device__ float g_mx[SLOTS*TI];
__device__ float g_sm[SLOTS*TI];
__device__ unsigned int g_cnt[NIT*LDIM];   // last-block tickets (self-resetting)

using u64 = unsigned long long;

__device__ __forceinline__ u64 ffma2(u64 a, u64 b, u64 c) {
    u64 d; asm("fma.rn.f32x2 %0, %1, %2, %3;" : "=l"(d) : "l"(a), "l"(b), "l"(c)); return d;
}
__device__ __forceinline__ u64 mul2(u64 a, u64 b) {
    u64 d; asm("mul.rn.f32x2 %0, %1, %2;" : "=l"(d) : "l"(a), "l"(b)); return d;
}
__device__ __forceinline__ u64 pack2(float x, float y) {
    u64 r; asm("mov.b64 %0, {%1, %2};" : "=l"(r) : "f"(x), "f"(y)); return r;
}
__device__ __forceinline__ float2 unpk(u64 v) {
    float2 f; asm("mov.b64 {%0, %1}, %2;" : "=f"(f.x), "=f"(f.y) : "l"(v)); return f;
}

__device__ __forceinline__ void cp16(uint32_t s, const void* g) {
    asm volatile("cp.async.cg.shared.global [%0], [%1], 16;" :: "r"(s), "l"(g));
}
#define CP_COMMIT() asm volatile("cp.async.commit_group;" ::: "memory")
#define CP_WAIT(n)  asm volatile("cp.async.wait_group %0;" :: "n"(n) : "memory")

// ==================== Kernel A: MLPs v5 (128 thr / 64-row tiles, 3 CTA/SM) ====================
#define MROWS 64
#define MTHR 128
#define AST 72     // activation row stride: 64 cols + 4-pad after col 32 + 4 tail
#define WST 68     // weight row stride: 64 outs + 4-pad after out 32

// mlp smem layout (floats)
#define M_BUFA 0
#define M_BUFB (MROWS*AST)            // 4608
#define M_WA   (2*MROWS*AST)          // 9216
#define M_WB   (M_WA + 64*WST)        // 13568
#define M_FLOATS (M_WB + 64*WST)      // 17920
#define M_BYTES (M_FLOATS*4)          // 71680

// async load of a 64x64 weight matrix into padded layout: W[c][o] at c*WST + o + (o>=32?4:0)
__device__ __forceinline__ void cp_wpad(const float* __restrict__ wg, uint32_t sW_s, int tid) {
    #pragma unroll
    for (int i = 0; i < 8; i++) {
        int idx = tid + i*MTHR;              // float4 index 0..1023
        int c = idx >> 4;
        int o = (idx & 15) * 4;
        uint32_t off = (uint32_t)(c*WST + o + (o >= 32 ? 4 : 0)) * 4u;
        cp16(sW_s + off, ((const float4*)wg) + idx);
    }
}

// one 64->64 layer + ReLU for 4 rows per thread (rows r, r+16, r+32, r+48).
__device__ __forceinline__ void layerv2(const float* __restrict__ in, const float* __restrict__ sW,
                                        const float* __restrict__ bg,
                                        float* outs, float* outg,
                                        int r, int o0, int wof, int row0) {
    float4 b0 = *(const float4*)&bg[o0];
    float4 b1 = *(const float4*)&bg[o0 + 4];
    u64 acc[4][4];
    #pragma unroll
    for (int k = 0; k < 4; k++) {
        acc[k][0] = pack2(b0.x, b0.y); acc[k][1] = pack2(b0.z, b0.w);
        acc[k][2] = pack2(b1.x, b1.y); acc[k][3] = pack2(b1.z, b1.w);
    }
    const float* in0 = in + r*AST;
    #pragma unroll
    for (int half = 0; half < 2; half++) {
        int coff = half * 36;                    // activation padded offset
        const float* wrow = sW + half*32*WST + wof;
        const float* ip = in0 + coff;
        #pragma unroll 8
        for (int c2 = 0; c2 < 32; c2++) {
            float h0 = ip[c2];
            float h1 = ip[16*AST + c2];
            float h2 = ip[32*AST + c2];
            float h3 = ip[48*AST + c2];
            ulonglong2 wa = *(const ulonglong2*)(wrow + c2*WST);
            ulonglong2 wb = *(const ulonglong2*)(wrow + c2*WST + 4);
            u64 hh;
            hh = pack2(h0, h0);
            acc[0][0] = ffma2(hh, wa.x, acc[0][0]); acc[0][1] = ffma2(hh, wa.y, acc[0][1]);
            acc[0][2] = ffma2(hh, wb.x, acc[0][2]); acc[0][3] = ffma2(hh, wb.y, acc[0][3]);
            hh = pack2(h1, h1);
            acc[1][0] = ffma2(hh, wa.x, acc[1][0]); acc[1][1] = ffma2(hh, wa.y, acc[1][1]);
            acc[1][2] = ffma2(hh, wb.x, acc[1][2]); acc[1][3] = ffma2(hh, wb.y, acc[1][3]);
            hh = pack2(h2, h2);
            acc[2][0] = ffma2(hh, wa.x, acc[2][0]); acc[2][1] = ffma2(hh, wa.y, acc[2][1]);
            acc[2][2] = ffma2(hh, wb.x, acc[2][2]); acc[2][3] = ffma2(hh, wb.y, acc[2][3]);
            hh = pack2(h3, h3);
            acc[3][0] = ffma2(hh, wa.x, acc[3][0]); acc[3][1] = ffma2(hh, wa.y, acc[3][1]);
            acc[3][2] = ffma2(hh, wb.x, acc[3][2]); acc[3][3] = ffma2(hh, wb.y, acc[3][3]);
        }
    }
    #pragma unroll
    for (int k = 0; k < 4; k++) {
        float2 f0 = unpk(acc[k][0]), f1 = unpk(acc[k][1]);
        float2 f2 = unpk(acc[k][2]), f3 = unpk(acc[k][3]);
        float4 lo = make_float4(fmaxf(f0.x,0.f), fmaxf(f0.y,0.f), fmaxf(f1.x,0.f), fmaxf(f1.y,0.f));
        float4 hi = make_float4(fmaxf(f2.x,0.f), fmaxf(f2.y,0.f), fmaxf(f3.x,0.f), fmaxf(f3.y,0.f));
        int rr = r + 16*k;
        if (outs) {
            float* d = &outs[rr*AST + wof];
            *(float4*)d = lo; *(float4*)(d + 4) = hi;
        }
        if (outg) {
            float* d = &outg[(row0 + rr)*HDIM + o0];
            *(float4*)d = lo; *(float4*)(d + 4) = hi;
        }
    }
}

__global__ __launch_bounds__(MTHR) void mlp_kernel(
    const float* __restrict__ h, const float* __restrict__ coord,
    const float* __restrict__ wq1, const float* __restrict__ bq1,
    const float* __restrict__ wq2, const float* __restrict__ bq2,
    const float* __restrict__ wk1, const float* __restrict__ bk1,
    const float* __restrict__ wk2, const float* __restrict__ bk2,
    const float* __restrict__ wv1, const float* __restrict__ bv1,
    const float* __restrict__ wv2, const float* __restrict__ bv2,
    const float* __restrict__ wc1, const float* __restrict__ bc1,
    const float* __restrict__ wc2)
{
    extern __shared__ float sm[];
    float* bufA = sm + M_BUFA;
    float* bufB = sm + M_BUFB;
    float* sWa  = sm + M_WA;
    float* sWb  = sm + M_WB;

    int tid = threadIdx.x;
    int row0 = blockIdx.x * MROWS;
    int chain = blockIdx.y;
    int r = tid >> 3;                 // 0..15
    int o0 = (tid & 7) * 8;
    int wof = o0 + (o0 >= 32 ? 4 : 0);

    uint32_t bufA_s = (uint32_t)__cvta_generic_to_shared(bufA);
    uint32_t sWa_s  = (uint32_t)__cvta_generic_to_shared(sWa);
    uint32_t sWb_s  = (uint32_t)__cvta_generic_to_shared(sWb);

    const float *w1, *b1, *w2, *b2;
    float* gout;
    if (chain == 0)      { w1 = wq1; b1 = bq1; w2 = wq2; b2 = bq2; gout = g_q; }
    else if (chain == 1) { w1 = wk1; b1 = bk1; w2 = wk2; b2 = bk2; gout = g_k; }
    else                 { w1 = wv1; b1 = bv1; w2 = wv2; b2 = bv2; gout = g_v; }

    // prologue: async W1 + h tile
    cp_wpad(w1, sWa_s, tid);
    #pragma unroll
    for (int k = 0; k < 4; k++) {
        int rr = r + 16*k;
        const float* src = &h[(row0 + rr)*HDIM + o0];
        uint32_t dst = bufA_s + (uint32_t)(rr*AST + wof)*4u;
        cp16(dst, src);
        cp16(dst + 16, src + 4);
    }
    CP_COMMIT();
    CP_WAIT(0);
    __syncthreads();

    // prefetch W2 during layer 1
    cp_wpad(w2, sWb_s, tid); CP_COMMIT();
    layerv2(bufA, sWa, b1, bufB, (float*)0, r, o0, wof, row0);
    CP_WAIT(0);
    __syncthreads();

    if (chain != 2) {
        layerv2(bufB, sWb, b2, (float*)0, gout, r, o0, wof, row0);
        return;
    }

    // chain 2: prefetch wc1 into sWa during layer 2
    cp_wpad(wc1, sWa_s, tid); CP_COMMIT();
    layerv2(bufB, sWb, b2, bufA, gout, r, o0, wof, row0);
    CP_WAIT(0);
    __syncthreads();

    // prefetch wc2 into sWb (compact 64x4 layout) during layer 3
    if (tid < 64) cp16(sWb_s + tid*16u, ((const float4*)wc2) + tid);
    CP_COMMIT();
    layerv2(bufA, sWa, bc1, bufB, (float*)0, r, o0, wof, row0);
    CP_WAIT(0);
    __syncthreads();

    // final: cmv = hidden @ wc2 (64 -> 4), 2 outputs per thread
    {
        int rr = tid >> 1;            // 0..63
        int ob = (tid & 1) * 2;
        float a0 = 0.f, a1 = 0.f;
        const float* inr = &bufB[rr*AST];
        const float* sW = sWb;
        #pragma unroll 8
        for (int c = 0; c < 32; c++) {
            float x = inr[c];
            a0 += x * sW[c*4 + ob];
            a1 += x * sW[c*4 + ob + 1];
        }
        #pragma unroll 8
        for (int c = 32; c < 64; c++) {
            float x = inr[c + 4];
            a0 += x * sW[c*4 + ob];
            a1 += x * sW[c*4 + ob + 1];
        }
        int row = row0 + rr;
        g_cmv[row*4 + ob]     = a0;
        g_cmv[row*4 + ob + 1] = a1;
        #pragma unroll
        for (int t = 0; t < 3; t++) {
            g_cmvc[row*12 + ob*3 + t]     = a0 * coord[row*12 + ob*3 + t];
            g_cmvc[row*12 + (ob+1)*3 + t] = a1 * coord[row*12 + (ob+1)*3 + t];
        }
    }
}

// ==================== Kernel B: flash attention partials + fused last-block combine ====================
#define KSTR 68   // multiple of 4: 16B alignment for float4/cp.async
#define SSTR 33
#define STG 81    // padded stage stride for combine (conflict-free)

#define OQT 0
#define OK  2048                    // 64 cols x 32 rows (also reused as combine stage: 32*81=2592 <= 64*68=4352)
#define OV  (OK + TJ*KSTR)          // 6400
#define OS  (OV + TJ*VW)            // 11520
#define OC  (OS + TJ*SSTR)          // 13632
#define OFLAG (OC + TI)             // 13664
#define B1_FLOATS (OFLAG + 1)       // 13665
#define B1_BYTES (B1_FLOATS*4)      // 54660

__device__ __forceinline__ void issue_k_tile(uint32_t kp_s, int jb, int l, int tid) {
    int j = tid >> 2, c0 = (tid & 3) * 16;
    const float* src = &g_k[((jb + j)*LDIM + l)*HDIM + c0];
    uint32_t d = kp_s + (uint32_t)(j*KSTR + c0)*4u;
    #pragma unroll
    for (int q4 = 0; q4 < 4; q4++) cp16(d + q4*16, src + q4*4);
}
__device__ __forceinline__ void issue_v_tile(uint32_t vt_s, int jb, int l, int tid) {
    int j = tid >> 2, c0 = (tid & 3) * 16;
    const float* src = &g_v[((jb + j)*LDIM + l)*HDIM + c0];
    uint32_t d = vt_s + (uint32_t)(j*VW + c0)*4u;
    #pragma unroll
    for (int q4 = 0; q4 < 4; q4++) cp16(d + q4*16, src + q4*4);
    if (tid < TJ) {
        int grow = (jb + tid)*LDIM + l;
        uint32_t dv = vt_s + (uint32_t)(tid*VW + 64)*4u;
        cp16(dv, &g_cmv[grow*4]);
        const float* cc = &g_cmvc[grow*12];
        cp16(dv + 16, cc);
        cp16(dv + 32, cc + 4);
        cp16(dv + 48, cc + 8);
    }
}

__global__ __launch_bounds__(256, 4) void attn_part_kernel(
    const float* __restrict__ hin, const float* __restrict__ coord,
    float* __restrict__ out)
{
    extern __shared__ float smf[];
    float* qT = smf + OQT;
    float* kp = smf + OK;
    float* vt = smf + OV;
    float* S  = smf + OS;
    float* cb = smf + OC;

    int tid = threadIdx.x;
    int it = blockIdx.x, l = blockIdx.y, sp = blockIdx.z;
    int i0 = it * TI;
    int j0 = sp * (TPS*TJ);

    uint32_t kp_s = (uint32_t)__cvta_generic_to_shared(kp);
    uint32_t vt_s = (uint32_t)__cvta_generic_to_shared(vt);

    // prologue: start async loads of tile 0
    issue_k_tile(kp_s, j0, l, tid); CP_COMMIT();
    issue_v_tile(vt_s, j0, l, tid); CP_COMMIT();

    // load q tile transposed: qT[c][r] (overlaps with async loads)
    {
        int r = tid >> 3, c0 = (tid & 7) * 8;
        const float* src = &g_q[((i0 + r)*LDIM + l)*HDIM + c0];
        float4 a = *(const float4*)src;
        float4 b = *(const float4*)(src + 4);
        float v8[8] = {a.x, a.y, a.z, a.w, b.x, b.y, b.z, b.w};
        #pragma unroll
        for (int u = 0; u < 8; u++) qT[(c0 + u)*TI + r] = v8[u];
    }

    int rg = tid & 7, jg = tid >> 3, r0 = rg * 4, jj = jg * 2;  // phase1 roles
    int row = tid >> 3, sub = tid & 7;                          // phase2 roles
    int ra = tid & 31, dg = tid >> 5;                           // phase3 roles
    int cbase = (dg < 4) ? dg*12 : 48 + (dg - 4)*8;             // 16B-aligned chunks

    float m_reg = -1e30f, s_reg = 0.f;
    u64 ac[6] = {0, 0, 0, 0, 0, 0};

    #pragma unroll
    for (int t = 0; t < TPS; t++) {
        int jb = j0 + t*TJ;

        CP_WAIT(1);            // K(t) complete (V(t) may still be in flight)
        __syncthreads();

        // ---- phase 1: scores -> S[j][r] (transposed) ----
        // per 4c: 1 k-LDS.128/row + 4 q-LDS.128 (one per c) + packs + FFMA2
        {
            u64 a00 = 0, a01 = 0, a10 = 0, a11 = 0;
            const float* kr0 = &kp[jj*KSTR];
            const float* kr1 = &kp[(jj + 1)*KSTR];
            #pragma unroll
            for (int c4 = 0; c4 < 64; c4 += 4) {
                float4 k0v = *(const float4*)&kr0[c4];
                float4 k1v = *(const float4*)&kr1[c4];
                #pragma unroll
                for (int u = 0; u < 4; u++) {
                    ulonglong2 q = *(const ulonglong2*)&qT[(c4 + u)*TI + r0];
                    float k0s = (&k0v.x)[u];
                    float k1s = (&k1v.x)[u];
                    u64 k0 = pack2(k0s, k0s);
                    u64 k1 = pack2(k1s, k1s);
                    a00 = ffma2(q.x, k0, a00);
                    a01 = ffma2(q.y, k0, a01);
                    a10 = ffma2(q.x, k1, a10);
                    a11 = ffma2(q.y, k1, a11);
                }
            }
            float2 f;
            f = unpk(a00); S[jj*SSTR + r0]     = f.x; S[jj*SSTR + r0 + 1]     = f.y;
            f = unpk(a01); S[jj*SSTR + r0 + 2] = f.x; S[jj*SSTR + r0 + 3]     = f.y;
            f = unpk(a10); S[(jj+1)*SSTR + r0]     = f.x; S[(jj+1)*SSTR + r0 + 1] = f.y;
            f = unpk(a11); S[(jj+1)*SSTR + r0 + 2] = f.x; S[(jj+1)*SSTR + r0 + 3] = f.y;
        }
        __syncthreads();

        // K buffer free: prefetch K(t+1)
        if (t < TPS-1) { issue_k_tile(kp_s, jb + TJ, l, tid); CP_COMMIT(); }

        // ---- phase 2: online softmax update ----
        {
            float tm = -1e30f;
            #pragma unroll
            for (int j = sub; j < TJ; j += 8) tm = fmaxf(tm, S[j*SSTR + row]);
            #pragma unroll
            for (int w = 4; w >= 1; w >>= 1) tm = fmaxf(tm, __shfl_xor_sync(0xffffffffu, tm, w));
            float newm = fmaxf(m_reg, tm);
            float cc = __expf(m_reg - newm);
            float ts = 0.f;
            #pragma unroll
            for (int j = sub; j < TJ; j += 8) {
                float e = __expf(S[j*SSTR + row] - newm);
                S[j*SSTR + row] = e;
                ts += e;
            }
            #pragma unroll
            for (int w = 4; w >= 1; w >>= 1) ts += __shfl_xor_sync(0xffffffffu, ts, w);
            s_reg = s_reg*cc + ts;
            m_reg = newm;
            if (sub == 0) cb[row] = cc;
        }
        if (t < TPS-1) { CP_WAIT(1); } else { CP_WAIT(0); }   // V(t) complete
        __syncthreads();

        // ---- phase 3: rescale + accumulate p @ [V|cmv|cmvc] ----
        {
            float cc = cb[ra];
            u64 c2 = pack2(cc, cc);
            const float* vb = vt + cbase;
            if (dg < 4) {
                #pragma unroll
                for (int u = 0; u < 6; u++) ac[u] = mul2(ac[u], c2);
                #pragma unroll 4
                for (int j = 0; j < TJ; j++) {
                    float p = S[j*SSTR + ra];
                    u64 p2 = pack2(p, p);
                    const float* vr = vb + j*VW;
                    ulonglong2 v01 = *(const ulonglong2*)(vr);
                    ulonglong2 v23 = *(const ulonglong2*)(vr + 4);
                    ulonglong2 v45 = *(const ulonglong2*)(vr + 8);
                    ac[0] = ffma2(p2, v01.x, ac[0]);
                    ac[1] = ffma2(p2, v01.y, ac[1]);
                    ac[2] = ffma2(p2, v23.x, ac[2]);
                    ac[3] = ffma2(p2, v23.y, ac[3]);
                    ac[4] = ffma2(p2, v45.x, ac[4]);
                    ac[5] = ffma2(p2, v45.y, ac[5]);
                }
            } else {
                #pragma unroll
                for (int u = 0; u < 4; u++) ac[u] = mul2(ac[u], c2);
                #pragma unroll 4
                for (int j = 0; j < TJ; j++) {
                    float p = S[j*SSTR + ra];
                    u64 p2 = pack2(p, p);
                    const float* vr = vb + j*VW;
                    ulonglong2 v01 = *(const ulonglong2*)(vr);
                    ulonglong2 v23 = *(const ulonglong2*)(vr + 4);
                    ac[0] = ffma2(p2, v01.x, ac[0]);
                    ac[1] = ffma2(p2, v01.y, ac[1]);
                    ac[2] = ffma2(p2, v23.x, ac[2]);
                    ac[3] = ffma2(p2, v23.y, ac[3]);
                }
            }
        }
        __syncthreads();

        // V buffer free: prefetch V(t+1)
        if (t < TPS-1) { issue_v_tile(vt_s, jb + TJ, l, tid); CP_COMMIT(); }
    }

    // ---- write partials ----
    int slot = (sp*LDIM + l)*NIT + it;
    if (sub == 0) {
        g_mx[slot*TI + row] = m_reg;
        g_sm[slot*TI + row] = s_reg;
    }
    {
        float* ga = &g_acc[(slot*VW + cbase)*TI + ra];
        if (dg < 4) {
            #pragma unroll
            for (int u = 0; u < 6; u++) {
                float2 f = unpk(ac[u]);
                ga[(u*2    )*TI] = f.x;
                ga[(u*2 + 1)*TI] = f.y;
            }
        } else {
            #pragma unroll
            for (int u = 0; u < 4; u++) {
                float2 f = unpk(ac[u]);
                ga[(u*2    )*TI] = f.x;
                ga[(u*2 + 1)*TI] = f.y;
            }
        }
    }

    // ---- last-block ticket: the final split block for this (it,l) combines ----
    __threadfence();
    __syncthreads();
    if (tid == 0) {
        unsigned int o = atomicAdd(&g_cnt[l*NIT + it], 1u);
        bool last = (o == JSPLIT - 1);
        smf[OFLAG] = last ? 1.f : 0.f;
        if (last) g_cnt[l*NIT + it] = 0;     // reset for next launch/replay
    }
    __syncthreads();
    if (smf[OFLAG] == 0.f) return;

    // ---- fused combine (reuses kp region as stage) ----
    {
        float* stage = smf + OK;
        int b0 = ((0*LDIM + l)*NIT + it);
        int b1 = ((1*LDIM + l)*NIT + it);
        int b2 = ((2*LDIM + l)*NIT + it);

        float m0 = g_mx[b0*TI + ra], m1 = g_mx[b1*TI + ra], m2 = g_mx[b2*TI + ra];
        float M = fmaxf(m0, fmaxf(m1, m2));
        float w0 = __expf(m0 - M), w1 = __expf(m1 - M), w2 = __expf(m2 - M);
        float denom = g_sm[b0*TI + ra]*w0 + g_sm[b1*TI + ra]*w1 + g_sm[b2*TI + ra]*w2;
        float inv = 1.f / denom;

        const float* a0 = &g_acc[(b0*VW + dg*10)*TI + ra];
        const float* a1 = &g_acc[(b1*VW + dg*10)*TI + ra];
        const float* a2 = &g_acc[(b2*VW + dg*10)*TI + ra];
        float* st = &stage[ra*STG + dg*10];
        #pragma unroll
        for (int u = 0; u < 10; u++)
            st[u] = (a0[u*TI]*w0 + a1[u*TI]*w1 + a2[u*TI]*w2) * inv;
        __syncthreads();

        // h output with residual
        {
            int r = tid >> 3, c0 = (tid & 7) * 8;
            int gi = ((it*TI + r)*LDIM + l)*HDIM + c0;
            const float* sg = &stage[r*STG + c0];
            float4 h0 = *(const float4*)&hin[gi];
            float4 h1 = *(const float4*)&hin[gi + 4];
            *(float4*)&out[gi] =
                make_float4(h0.x + sg[0], h0.y + sg[1], h0.z + sg[2], h0.w + sg[3]);
            *(float4*)&out[gi + 4] =
                make_float4(h1.x + sg[4], h1.y + sg[5], h1.z + sg[6], h1.w + sg[7]);
        }
        // coord output: out = coord*(1+S1[k]) - S2[k][t]
        for (int e = tid; e < TI*12; e += 256) {
            int r = e / 12, idx = e % 12, k = idx / 3;
            float S1 = stage[r*STG + 64 + k];
            float S2 = stage[r*STG + 68 + idx];
            int off = ((it*TI + r)*LDIM + l)*12 + idx;
            out[COUT_OFF + off] = coord[off] * (1.f + S1) - S2;
        }
    }
}

// ==================== launch ====================
extern "C" void kernel_launch(void* const* d_in, const int* in_sizes, int n_in,
                              void* d_out, int out_size) {
    const float* h     = (const float*)d_in[0];
    const float* coord = (const float*)d_in[1];
    const float* wq1 = (const float*)d_in[2];
    const float* bq1 = (const float*)d_in[3];
    const float* wq2 = (const float*)d_in[4];
    const float* bq2 = (const float*)d_in[5];
    const float* wk1 = (const float*)d_in[6];
    const float* bk1 = (const float*)d_in[7];
    const float* wk2 = (const float*)d_in[8];
    const float* bk2 = (const float*)d_in[9];
    const float* wv1 = (const float*)d_in[10];
    const float* bv1 = (const float*)d_in[11];
    const float* wv2 = (const float*)d_in[12];
    const float* bv2 = (const float*)d_in[13];
    const float* wc1 = (const float*)d_in[14];
    const float* bc1 = (const float*)d_in[15];
    const float* wc2 = (const float*)d_in[16];
    float* out = (float*)d_out;

    cudaFuncSetAttribute(mlp_kernel, cudaFuncAttributeMaxDynamicSharedMemorySize, M_BYTES);
    mlp_kernel<<<dim3(NROWS/MROWS, 3), MTHR, M_BYTES>>>(h, coord, wq1, bq1, wq2, bq2,
                                                        wk1, bk1, wk2, bk2, wv1, bv1, wv2, bv2,
                                                        wc1, bc1, wc2);

    cudaFuncSetAttribute(attn_part_kernel, cudaFuncAttributeMaxDynamicSharedMemorySize, B1_BYTES);
    attn_part_kernel<<<dim3(NIT, LDIM, JSPLIT), 256, B1_BYTES>>>(h, coord, out);
}